// round 10
// baseline (speedup 1.0000x reference)
#include <cuda_runtime.h>
#include <cuda_bf16.h>
#include <cstdint>

#define N_NODES 100000
#define N_EDGES 800000
#define F_IN    128
#define C_MID   256
#define H_DIM   128
#define O_DIM   6
#define NEG_SLOPE 0.2f

#define E_TOT (N_EDGES + N_NODES)
#define SCAN_BLK 1024
#define N_SCAN_BLKS ((N_NODES + SCAN_BLK - 1) / SCAN_BLK)   // 98

#define PITCH 136                        // bf16 elems per smem row (conflict-free)
#define PLANE (128 * PITCH)              // elems per plane
#define SM_SMALL 8192                    // bytes reserved for vectors
#define SM_TOTAL (SM_SMALL + 4 * PLANE * 2)   // 147456 bytes

// ---------------- device scratch ----------------
__device__ float g_xw[(size_t)N_NODES * C_MID];
__device__ float g_s[N_NODES];
__device__ float g_d[N_NODES];
__device__ float g_w[E_TOT];
__device__ float g_winv[N_NODES];
__device__ int   g_count[N_NODES];
__device__ int   g_rowptr[N_NODES];
__device__ int   g_fill[N_NODES];
__device__ int   g_partial[N_SCAN_BLKS];
__device__ int   g_ecol[E_TOT];
// pre-split, pre-transposed bf16 B-operand planes ([N][PITCH] row-major, K contig)
__device__ __nv_bfloat16 g_b1hi[256 * PITCH];
__device__ __nv_bfloat16 g_b1lo[256 * PITCH];
__device__ __nv_bfloat16 g_b2hi[2 * 128 * PITCH];
__device__ __nv_bfloat16 g_b2lo[2 * 128 * PITCH];

// ---------------- helpers ----------------
__device__ __forceinline__ void mma_bf16(float* c, const uint32_t* a, uint32_t b0, uint32_t b1) {
    asm volatile(
        "mma.sync.aligned.m16n8k16.row.col.f32.bf16.bf16.f32 "
        "{%0,%1,%2,%3}, {%4,%5,%6,%7}, {%8,%9}, {%0,%1,%2,%3};"
        : "+f"(c[0]), "+f"(c[1]), "+f"(c[2]), "+f"(c[3])
        : "r"(a[0]), "r"(a[1]), "r"(a[2]), "r"(a[3]), "r"(b0), "r"(b1));
}

__device__ __forceinline__ void split_store(__nv_bfloat16* hi, __nv_bfloat16* lo,
                                            int off, float x, float y) {
    const __nv_bfloat16 hx = __float2bfloat16(x), hy = __float2bfloat16(y);
    const float rx = x - __bfloat162float(hx), ry = y - __bfloat162float(hy);
    *reinterpret_cast<__nv_bfloat162*>(hi + off) = __nv_bfloat162{hx, hy};
    *reinterpret_cast<__nv_bfloat162*>(lo + off) =
        __nv_bfloat162{__float2bfloat16(rx), __float2bfloat16(ry)};
}

// ---------------- fused init + B-operand prep ----------------
__global__ void initprep_kernel(const float* __restrict__ W, const float* __restrict__ W2) {
    const int i = blockIdx.x * 256 + threadIdx.x;
    if (i < N_NODES) {
        g_count[i] = 0; g_fill[i] = 0; g_s[i] = 0.f; g_d[i] = 0.f;
    }
    if (i < 256 * 128) {                      // GEMM1: B[n][k] = W[k][n]
        const int n = i >> 7, k = i & 127;
        const float v = W[(size_t)k * C_MID + n];
        const __nv_bfloat16 h = __float2bfloat16(v);
        g_b1hi[n * PITCH + k] = h;
        g_b1lo[n * PITCH + k] = __float2bfloat16(v - __bfloat162float(h));
    } else if (i < 2 * 256 * 128) {           // GEMM2: B[n][k] = W_fc2[k][n], 2 K-chunks
        const int idx = i - 256 * 128;
        const int k = idx & 255, n = idx >> 8;
        const float v = W2[(size_t)k * H_DIM + n];
        const __nv_bfloat16 h = __float2bfloat16(v);
        const int off = (k >> 7) * 128 * PITCH + n * PITCH + (k & 127);
        g_b2hi[off] = h;
        g_b2lo[off] = __float2bfloat16(v - __bfloat162float(h));
    }
}

// ---------------- CSR build ----------------
__global__ void hist_kernel(const int* __restrict__ ei) {
    const int e = blockIdx.x * blockDim.x + threadIdx.x;
    if (e >= E_TOT) return;
    const int dst = (e < N_EDGES) ? ei[N_EDGES + e] : (e - N_EDGES);
    atomicAdd(&g_count[dst], 1);
}
__global__ void scan1_kernel() {
    __shared__ int sh[SCAN_BLK];
    const int i = blockIdx.x * SCAN_BLK + threadIdx.x;
    const int v = (i < N_NODES) ? g_count[i] : 0;
    sh[threadIdx.x] = v;
    __syncthreads();
    for (int off = 1; off < SCAN_BLK; off <<= 1) {
        const int t = (threadIdx.x >= off) ? sh[threadIdx.x - off] : 0;
        __syncthreads();
        sh[threadIdx.x] += t;
        __syncthreads();
    }
    if (i < N_NODES) g_rowptr[i] = sh[threadIdx.x] - v;
    if (threadIdx.x == SCAN_BLK - 1) g_partial[blockIdx.x] = sh[SCAN_BLK - 1];
}
__global__ void scan2_kernel() {
    __shared__ int sh[128];
    const int t = threadIdx.x;
    const int v = (t < N_SCAN_BLKS) ? g_partial[t] : 0;
    sh[t] = v;
    __syncthreads();
    for (int off = 1; off < 128; off <<= 1) {
        const int u = (t >= off) ? sh[t - off] : 0;
        __syncthreads();
        sh[t] += u;
        __syncthreads();
    }
    if (t < N_SCAN_BLKS) g_partial[t] = sh[t] - v;
}
__global__ void scan3_kernel() {
    const int i = blockIdx.x * blockDim.x + threadIdx.x;
    if (i < N_NODES) g_rowptr[i] += g_partial[i >> 10];
}
__global__ void scatter_kernel(const int* __restrict__ ei) {
    const int e = blockIdx.x * blockDim.x + threadIdx.x;
    if (e >= E_TOT) return;
    int src, dst;
    if (e < N_EDGES) { src = ei[e]; dst = ei[N_EDGES + e]; }
    else             { src = dst = e - N_EDGES; }
    const int pos = g_rowptr[dst] + atomicAdd(&g_fill[dst], 1);
    g_ecol[pos] = src;
}

// ---------------- edge weights: w[e] = exp(lrelu(s[src]+d[dst])), winv[n]=1/sum ----
__global__ __launch_bounds__(256) void weight_kernel()
{
    const int node = blockIdx.x * 8 + (threadIdx.x >> 5);
    const int lane = threadIdx.x & 31;
    if (node >= N_NODES) return;
    const int beg = g_rowptr[node];
    const int cnt = g_count[node];
    const float dterm = g_d[node];
    float wsum = 0.f;
    for (int k = lane; k < cnt; k += 32) {
        const int src = g_ecol[beg + k];
        float e = g_s[src] + dterm;
        e = (e > 0.f) ? e : NEG_SLOPE * e;
        const float w = __expf(e);          // softmax max-shift cancels exactly
        g_w[beg + k] = w;
        wsum += w;
    }
#pragma unroll
    for (int o = 16; o > 0; o >>= 1)
        wsum += __shfl_xor_sync(0xffffffffu, wsum, o);
    if (lane == 0) g_winv[node] = 1.f / wsum;   // cnt >= 1 (self-loop)
}

// ---------------- GEMM1: bf16 3-pass tensor cores (verified R8, unchanged) ----------
__global__ __launch_bounds__(256) void gemm1_bf16(
    const float* __restrict__ A,
    const __nv_bfloat16* __restrict__ Bhi, const __nv_bfloat16* __restrict__ Blo,
    float* __restrict__ C,
    const float* __restrict__ v1, const float* __restrict__ v2, int M)
{
    extern __shared__ char smem[];
    __nv_bfloat16* Ahi = reinterpret_cast<__nv_bfloat16*>(smem + SM_SMALL);
    __nv_bfloat16* Alo = Ahi + PLANE;
    __nv_bfloat16* Bhs = Alo + PLANE;
    __nv_bfloat16* Bls = Bhs + PLANE;
    float* sv1 = reinterpret_cast<float*>(smem);
    float* sv2 = reinterpret_cast<float*>(smem + 3072);

    const int tid = threadIdx.x;
    const int lane = tid & 31;
    const int warp = tid >> 5;
    const int warp_m = warp >> 2, warp_n = warp & 3;
    const int row0 = blockIdx.y * 128;
    const int col0 = blockIdx.x * 128;
    const int gq = lane >> 2;
    const int c2 = (lane & 3) * 2;

    if (tid < 128) { sv1[tid] = v1[col0 + tid]; sv2[tid] = v2[col0 + tid]; }

    float acc[4][4][4];
#pragma unroll
    for (int mt = 0; mt < 4; mt++)
#pragma unroll
        for (int nt = 0; nt < 4; nt++)
#pragma unroll
            for (int q = 0; q < 4; q++) acc[mt][nt][q] = 0.f;

    // stage A
    {
        const int r = tid >> 1, h = (tid & 1) * 64;
        const bool ok = (row0 + r) < M;
        const float4* ap = reinterpret_cast<const float4*>(A + (size_t)(row0 + r) * F_IN + h);
#pragma unroll
        for (int j = 0; j < 16; j++) {
            float4 v = make_float4(0.f, 0.f, 0.f, 0.f);
            if (ok) v = ap[j];
            const int off = r * PITCH + h + 4 * j;
            split_store(Ahi, Alo, off, v.x, v.y);
            split_store(Ahi, Alo, off + 2, v.z, v.w);
        }
    }
    // stage B
    {
        const size_t boff = (size_t)col0 * PITCH;
        const float4* sh = reinterpret_cast<const float4*>(Bhi + boff);
        const float4* sl = reinterpret_cast<const float4*>(Blo + boff);
        float4* dh = reinterpret_cast<float4*>(Bhs);
        float4* dl = reinterpret_cast<float4*>(Bls);
        for (int i = tid; i < PLANE / 8; i += 256) { dh[i] = sh[i]; dl[i] = sl[i]; }
    }
    __syncthreads();

#pragma unroll
    for (int ks = 0; ks < 8; ks++) {
        const int kk = ks * 16;
        uint32_t ahi[4][4], alo[4][4];
#pragma unroll
        for (int mt = 0; mt < 4; mt++) {
            const int r = warp_m * 64 + mt * 16 + gq;
            ahi[mt][0] = *reinterpret_cast<const uint32_t*>(&Ahi[r * PITCH + kk + c2]);
            ahi[mt][1] = *reinterpret_cast<const uint32_t*>(&Ahi[(r + 8) * PITCH + kk + c2]);
            ahi[mt][2] = *reinterpret_cast<const uint32_t*>(&Ahi[r * PITCH + kk + c2 + 8]);
            ahi[mt][3] = *reinterpret_cast<const uint32_t*>(&Ahi[(r + 8) * PITCH + kk + c2 + 8]);
            alo[mt][0] = *reinterpret_cast<const uint32_t*>(&Alo[r * PITCH + kk + c2]);
            alo[mt][1] = *reinterpret_cast<const uint32_t*>(&Alo[(r + 8) * PITCH + kk + c2]);
            alo[mt][2] = *reinterpret_cast<const uint32_t*>(&Alo[r * PITCH + kk + c2 + 8]);
            alo[mt][3] = *reinterpret_cast<const uint32_t*>(&Alo[(r + 8) * PITCH + kk + c2 + 8]);
        }
        uint32_t bhi[4][2], blo[4][2];
#pragma unroll
        for (int nt = 0; nt < 4; nt++) {
            const int n = warp_n * 32 + nt * 8 + gq;
            bhi[nt][0] = *reinterpret_cast<const uint32_t*>(&Bhs[n * PITCH + kk + c2]);
            bhi[nt][1] = *reinterpret_cast<const uint32_t*>(&Bhs[n * PITCH + kk + c2 + 8]);
            blo[nt][0] = *reinterpret_cast<const uint32_t*>(&Bls[n * PITCH + kk + c2]);
            blo[nt][1] = *reinterpret_cast<const uint32_t*>(&Bls[n * PITCH + kk + c2 + 8]);
        }
#pragma unroll
        for (int mt = 0; mt < 4; mt++)
#pragma unroll
            for (int nt = 0; nt < 4; nt++) {
                mma_bf16(acc[mt][nt], ahi[mt], bhi[nt][0], bhi[nt][1]);
                mma_bf16(acc[mt][nt], ahi[mt], blo[nt][0], blo[nt][1]);
                mma_bf16(acc[mt][nt], alo[mt], bhi[nt][0], bhi[nt][1]);
            }
    }

    // store C + fused a_src/a_dst dots
#pragma unroll
    for (int mt = 0; mt < 4; mt++) {
        const int r = row0 + warp_m * 64 + mt * 16 + gq;
#pragma unroll
        for (int nt = 0; nt < 4; nt++) {
            const int c = col0 + warp_n * 32 + nt * 8 + c2;
            if (r < M)
                *reinterpret_cast<float2*>(C + (size_t)r * C_MID + c) =
                    make_float2(acc[mt][nt][0], acc[mt][nt][1]);
            if (r + 8 < M)
                *reinterpret_cast<float2*>(C + (size_t)(r + 8) * C_MID + c) =
                    make_float2(acc[mt][nt][2], acc[mt][nt][3]);
        }
    }
    float avv[4][2], dvv[4][2];
#pragma unroll
    for (int nt = 0; nt < 4; nt++) {
        const int lc = warp_n * 32 + nt * 8 + c2;
        avv[nt][0] = sv1[lc]; avv[nt][1] = sv1[lc + 1];
        dvv[nt][0] = sv2[lc]; dvv[nt][1] = sv2[lc + 1];
    }
#pragma unroll
    for (int mt = 0; mt < 4; mt++) {
        float ps0 = 0.f, pd0 = 0.f, ps8 = 0.f, pd8 = 0.f;
#pragma unroll
        for (int nt = 0; nt < 4; nt++) {
            ps0 = fmaf(acc[mt][nt][0], avv[nt][0], fmaf(acc[mt][nt][1], avv[nt][1], ps0));
            pd0 = fmaf(acc[mt][nt][0], dvv[nt][0], fmaf(acc[mt][nt][1], dvv[nt][1], pd0));
            ps8 = fmaf(acc[mt][nt][2], avv[nt][0], fmaf(acc[mt][nt][3], avv[nt][1], ps8));
            pd8 = fmaf(acc[mt][nt][2], dvv[nt][0], fmaf(acc[mt][nt][3], dvv[nt][1], pd8));
        }
#pragma unroll
        for (int off = 1; off <= 2; off <<= 1) {
            ps0 += __shfl_xor_sync(0xffffffffu, ps0, off);
            pd0 += __shfl_xor_sync(0xffffffffu, pd0, off);
            ps8 += __shfl_xor_sync(0xffffffffu, ps8, off);
            pd8 += __shfl_xor_sync(0xffffffffu, pd8, off);
        }
        if ((lane & 3) == 0) {
            const int r = row0 + warp_m * 64 + mt * 16 + gq;
            if (r < M)     { atomicAdd(&g_s[r], ps0);     atomicAdd(&g_d[r], pd0); }
            if (r + 8 < M) { atomicAdd(&g_s[r + 8], ps8); atomicAdd(&g_d[r + 8], pd8); }
        }
    }
}

// ---------------- GEMM2 with fused aggregation A-staging ----------------
// Per chunk (128-col half of C_MID): each warp aggregates 16 nodes directly
// into the smem A hi/lo planes (softmax-weighted gather + bias + relu), then
// the bf16 3-pass mma runs. h2 is never materialized in global memory.
__global__ __launch_bounds__(256) void gemm2_fused(
    const __nv_bfloat16* __restrict__ Bhi, const __nv_bfloat16* __restrict__ Blo,
    const float* __restrict__ bias_gat,   // b       (256)
    const float* __restrict__ bias_fc2,   // b_fc2   (128)
    const float* __restrict__ W_out, const float* __restrict__ b_out,
    float* __restrict__ outp, int M)
{
    extern __shared__ char smem[];
    __nv_bfloat16* Ahi = reinterpret_cast<__nv_bfloat16*>(smem + SM_SMALL);
    __nv_bfloat16* Alo = Ahi + PLANE;
    __nv_bfloat16* Bhs = Alo + PLANE;
    __nv_bfloat16* Bls = Bhs + PLANE;
    float* sv1 = reinterpret_cast<float*>(smem);          // W_out: 768 floats
    float* sv2 = reinterpret_cast<float*>(smem + 3072);   // b_fc2: 128 floats
    float* svb = reinterpret_cast<float*>(smem + 4096);   // b:     256 floats

    const int tid = threadIdx.x;
    const int lane = tid & 31;
    const int warp = tid >> 5;
    const int warp_m = warp >> 2, warp_n = warp & 3;
    const int row0 = blockIdx.x * 128;
    const int gq = lane >> 2;
    const int c2 = (lane & 3) * 2;

#pragma unroll
    for (int i = 0; i < 3; i++) sv1[tid + 256 * i] = W_out[tid + 256 * i];
    if (tid < 128) sv2[tid] = bias_fc2[tid];
    svb[tid] = bias_gat[tid];
    __syncthreads();

    float acc[4][4][4];
#pragma unroll
    for (int mt = 0; mt < 4; mt++)
#pragma unroll
        for (int nt = 0; nt < 4; nt++)
#pragma unroll
            for (int q = 0; q < 4; q++) acc[mt][nt][q] = 0.f;

    for (int chunk = 0; chunk < 2; chunk++) {
        // ---- fused aggregation A-staging: warp aggregates 16 nodes ----
        {
            const float4 bb = reinterpret_cast<const float4*>(svb)[chunk * 32 + lane];
            for (int i = 0; i < 16; i++) {
                const int rl = warp * 16 + i;
                const int node = row0 + rl;
                float4 a4 = make_float4(0.f, 0.f, 0.f, 0.f);
                if (node < M) {
                    const int beg = g_rowptr[node];
                    const int cnt = g_count[node];
                    for (int k = 0; k < cnt; k++) {
                        const int src = g_ecol[beg + k];    // warp-broadcast
                        const float w = g_w[beg + k];       // warp-broadcast
                        const float4 v = *reinterpret_cast<const float4*>(
                            g_xw + (size_t)src * C_MID + chunk * 128 + lane * 4);
                        a4.x = fmaf(w, v.x, a4.x);
                        a4.y = fmaf(w, v.y, a4.y);
                        a4.z = fmaf(w, v.z, a4.z);
                        a4.w = fmaf(w, v.w, a4.w);
                    }
                    const float inv = g_winv[node];
                    a4.x = fmaxf(fmaf(a4.x, inv, bb.x), 0.f);
                    a4.y = fmaxf(fmaf(a4.y, inv, bb.y), 0.f);
                    a4.z = fmaxf(fmaf(a4.z, inv, bb.z), 0.f);
                    a4.w = fmaxf(fmaf(a4.w, inv, bb.w), 0.f);
                }
                const int off = rl * PITCH + lane * 4;
                split_store(Ahi, Alo, off, a4.x, a4.y);
                split_store(Ahi, Alo, off + 2, a4.z, a4.w);
            }
        }
        // ---- stage B ----
        {
            const size_t boff = (size_t)chunk * 128 * PITCH;
            const float4* sh = reinterpret_cast<const float4*>(Bhi + boff);
            const float4* sl = reinterpret_cast<const float4*>(Blo + boff);
            float4* dh = reinterpret_cast<float4*>(Bhs);
            float4* dl = reinterpret_cast<float4*>(Bls);
            for (int i = tid; i < PLANE / 8; i += 256) { dh[i] = sh[i]; dl[i] = sl[i]; }
        }
        __syncthreads();

#pragma unroll
        for (int ks = 0; ks < 8; ks++) {
            const int kk = ks * 16;
            uint32_t ahi[4][4], alo[4][4];
#pragma unroll
            for (int mt = 0; mt < 4; mt++) {
                const int r = warp_m * 64 + mt * 16 + gq;
                ahi[mt][0] = *reinterpret_cast<const uint32_t*>(&Ahi[r * PITCH + kk + c2]);
                ahi[mt][1] = *reinterpret_cast<const uint32_t*>(&Ahi[(r + 8) * PITCH + kk + c2]);
                ahi[mt][2] = *reinterpret_cast<const uint32_t*>(&Ahi[r * PITCH + kk + c2 + 8]);
                ahi[mt][3] = *reinterpret_cast<const uint32_t*>(&Ahi[(r + 8) * PITCH + kk + c2 + 8]);
                alo[mt][0] = *reinterpret_cast<const uint32_t*>(&Alo[r * PITCH + kk + c2]);
                alo[mt][1] = *reinterpret_cast<const uint32_t*>(&Alo[(r + 8) * PITCH + kk + c2]);
                alo[mt][2] = *reinterpret_cast<const uint32_t*>(&Alo[r * PITCH + kk + c2 + 8]);
                alo[mt][3] = *reinterpret_cast<const uint32_t*>(&Alo[(r + 8) * PITCH + kk + c2 + 8]);
            }
            uint32_t bhi[4][2], blo[4][2];
#pragma unroll
            for (int nt = 0; nt < 4; nt++) {
                const int n = warp_n * 32 + nt * 8 + gq;
                bhi[nt][0] = *reinterpret_cast<const uint32_t*>(&Bhs[n * PITCH + kk + c2]);
                bhi[nt][1] = *reinterpret_cast<const uint32_t*>(&Bhs[n * PITCH + kk + c2 + 8]);
                blo[nt][0] = *reinterpret_cast<const uint32_t*>(&Bls[n * PITCH + kk + c2]);
                blo[nt][1] = *reinterpret_cast<const uint32_t*>(&Bls[n * PITCH + kk + c2 + 8]);
            }
#pragma unroll
            for (int mt = 0; mt < 4; mt++)
#pragma unroll
                for (int nt = 0; nt < 4; nt++) {
                    mma_bf16(acc[mt][nt], ahi[mt], bhi[nt][0], bhi[nt][1]);
                    mma_bf16(acc[mt][nt], ahi[mt], blo[nt][0], blo[nt][1]);
                    mma_bf16(acc[mt][nt], alo[mt], bhi[nt][0], bhi[nt][1]);
                }
        }
        __syncthreads();
    }

    // ---- epilogue: h3 = relu(acc + b_fc2); out = h3 @ W_out + b_out ----
    float bb[4][2];
#pragma unroll
    for (int nt = 0; nt < 4; nt++) {
        const int lc = warp_n * 32 + nt * 8 + c2;
        bb[nt][0] = sv2[lc]; bb[nt][1] = sv2[lc + 1];
    }
#pragma unroll
    for (int mt = 0; mt < 4; mt++)
#pragma unroll
        for (int nt = 0; nt < 4; nt++) {
            acc[mt][nt][0] = fmaxf(acc[mt][nt][0] + bb[nt][0], 0.f);
            acc[mt][nt][1] = fmaxf(acc[mt][nt][1] + bb[nt][1], 0.f);
            acc[mt][nt][2] = fmaxf(acc[mt][nt][2] + bb[nt][0], 0.f);
            acc[mt][nt][3] = fmaxf(acc[mt][nt][3] + bb[nt][1], 0.f);
        }
    float* red = reinterpret_cast<float*>(smem + SM_SMALL);   // [128][25]
#pragma unroll
    for (int o = 0; o < O_DIM; o++) {
        float wv0[4], wv1[4];
#pragma unroll
        for (int nt = 0; nt < 4; nt++) {
            const int lc = warp_n * 32 + nt * 8 + c2;
            wv0[nt] = sv1[lc * O_DIM + o];
            wv1[nt] = sv1[(lc + 1) * O_DIM + o];
        }
#pragma unroll
        for (int mt = 0; mt < 4; mt++) {
            float p0 = 0.f, p8 = 0.f;
#pragma unroll
            for (int nt = 0; nt < 4; nt++) {
                p0 = fmaf(acc[mt][nt][0], wv0[nt], fmaf(acc[mt][nt][1], wv1[nt], p0));
                p8 = fmaf(acc[mt][nt][2], wv0[nt], fmaf(acc[mt][nt][3], wv1[nt], p8));
            }
#pragma unroll
            for (int off = 1; off <= 2; off <<= 1) {
                p0 += __shfl_xor_sync(0xffffffffu, p0, off);
                p8 += __shfl_xor_sync(0xffffffffu, p8, off);
            }
            if ((lane & 3) == 0) {
                const int rl = warp_m * 64 + mt * 16 + gq;
                red[rl * 25 + warp_n * 6 + o] = p0;
                red[(rl + 8) * 25 + warp_n * 6 + o] = p8;
            }
        }
    }
    __syncthreads();
    if (tid < 128) {
        const int r = row0 + tid;
        if (r < M) {
#pragma unroll
            for (int o = 0; o < O_DIM; o++) {
                const float s = red[tid * 25 + o] + red[tid * 25 + 6 + o]
                              + red[tid * 25 + 12 + o] + red[tid * 25 + 18 + o];
                outp[(size_t)r * O_DIM + o] = s + b_out[o];
            }
        }
    }
}

// ---------------- launch ----------------
extern "C" void kernel_launch(void* const* d_in, const int* in_sizes, int n_in,
                              void* d_out, int out_size)
{
    const float* x      = (const float*)d_in[0];
    const int*   ei     = (const int*)  d_in[1];
    const float* W      = (const float*)d_in[2];
    const float* a_src  = (const float*)d_in[3];
    const float* a_dst  = (const float*)d_in[4];
    const float* b      = (const float*)d_in[5];
    const float* W_fc2  = (const float*)d_in[6];
    const float* b_fc2  = (const float*)d_in[7];
    const float* W_out  = (const float*)d_in[8];
    const float* b_out  = (const float*)d_in[9];
    float* out = (float*)d_out;

    float* xw;
    __nv_bfloat16 *b1h, *b1l, *b2h, *b2l;
    cudaGetSymbolAddress((void**)&xw,  g_xw);
    cudaGetSymbolAddress((void**)&b1h, g_b1hi);
    cudaGetSymbolAddress((void**)&b1l, g_b1lo);
    cudaGetSymbolAddress((void**)&b2h, g_b2hi);
    cudaGetSymbolAddress((void**)&b2l, g_b2lo);

    static bool inited = false;
    if (!inited) {
        cudaFuncSetAttribute(gemm1_bf16, cudaFuncAttributeMaxDynamicSharedMemorySize, SM_TOTAL);
        cudaFuncSetAttribute(gemm2_fused, cudaFuncAttributeMaxDynamicSharedMemorySize, SM_TOTAL);
        inited = true;
    }

    const int nblk = (N_NODES + 127) / 128;   // 782

    // 1) fused init + B prep
    initprep_kernel<<<(N_NODES + 255) / 256, 256>>>(W, W_fc2);

    // 2) CSR build
    hist_kernel<<<(E_TOT + 255) / 256, 256>>>(ei);
    scan1_kernel<<<N_SCAN_BLKS, SCAN_BLK>>>();
    scan2_kernel<<<1, 128>>>();
    scan3_kernel<<<(N_NODES + 255) / 256, 256>>>();
    scatter_kernel<<<(E_TOT + 255) / 256, 256>>>(ei);

    // 3) xw = x @ W (bf16 3-pass tensor cores) + fused s/d dots
    {
        dim3 grid(C_MID / 128, nblk);
        gemm1_bf16<<<grid, 256, SM_TOTAL>>>(x, b1h, b1l, xw, a_src, a_dst, N_NODES);
    }

    // 4) edge softmax weights
    weight_kernel<<<(N_NODES + 7) / 8, 256>>>();

    // 5) GEMM2 with fused aggregation (h2 never hits global memory)
    gemm2_fused<<<nblk, 256, SM_TOTAL>>>(b2h, b2l, b, b_fc2, W_out, b_out, out, N_NODES);
}

// round 11
// speedup vs baseline: 1.5199x; 1.5199x over previous
#include <cuda_runtime.h>
#include <cuda_bf16.h>
#include <cstdint>

#define N_NODES 100000
#define N_EDGES 800000
#define F_IN    128
#define C_MID   256
#define H_DIM   128
#define O_DIM   6
#define NEG_SLOPE 0.2f

#define E_TOT (N_EDGES + N_NODES)
#define SCAN_BLK 1024
#define N_SCAN_BLKS ((N_NODES + SCAN_BLK - 1) / SCAN_BLK)   // 98

#define PITCH 136                        // bf16 elems per smem row (conflict-free)
#define PLANE (128 * PITCH)              // elems per plane
#define SM_SMALL 4096                    // bytes reserved for vectors
#define SM_TOTAL (SM_SMALL + 4 * PLANE * 2)   // 143360 bytes

// ---------------- device scratch ----------------
__device__ float g_xw[(size_t)N_NODES * C_MID];
__device__ float g_gat[(size_t)N_NODES * C_MID];
__device__ float g_s[N_NODES];
__device__ float g_d[N_NODES];
__device__ float g_w[E_TOT];
__device__ float g_winv[N_NODES];
__device__ int   g_count[N_NODES];
__device__ int   g_rowptr[N_NODES];
__device__ int   g_fill[N_NODES];
__device__ int   g_partial[N_SCAN_BLKS];
__device__ int   g_ecol[E_TOT];
// pre-split, pre-transposed bf16 B-operand planes ([N][PITCH] row-major, K contig)
__device__ __nv_bfloat16 g_b1hi[256 * PITCH];
__device__ __nv_bfloat16 g_b1lo[256 * PITCH];
__device__ __nv_bfloat16 g_b2hi[2 * 128 * PITCH];
__device__ __nv_bfloat16 g_b2lo[2 * 128 * PITCH];

// ---------------- helpers ----------------
__device__ __forceinline__ void mma_bf16(float* c, const uint32_t* a, uint32_t b0, uint32_t b1) {
    asm volatile(
        "mma.sync.aligned.m16n8k16.row.col.f32.bf16.bf16.f32 "
        "{%0,%1,%2,%3}, {%4,%5,%6,%7}, {%8,%9}, {%0,%1,%2,%3};"
        : "+f"(c[0]), "+f"(c[1]), "+f"(c[2]), "+f"(c[3])
        : "r"(a[0]), "r"(a[1]), "r"(a[2]), "r"(a[3]), "r"(b0), "r"(b1));
}

__device__ __forceinline__ void split_store(__nv_bfloat16* hi, __nv_bfloat16* lo,
                                            int off, float x, float y) {
    const __nv_bfloat16 hx = __float2bfloat16(x), hy = __float2bfloat16(y);
    const float rx = x - __bfloat162float(hx), ry = y - __bfloat162float(hy);
    *reinterpret_cast<__nv_bfloat162*>(hi + off) = __nv_bfloat162{hx, hy};
    *reinterpret_cast<__nv_bfloat162*>(lo + off) =
        __nv_bfloat162{__float2bfloat16(rx), __float2bfloat16(ry)};
}

// ---------------- fused init + B-operand prep ----------------
__global__ void initprep_kernel(const float* __restrict__ W, const float* __restrict__ W2) {
    const int i = blockIdx.x * 256 + threadIdx.x;
    if (i < N_NODES) {
        g_count[i] = 0; g_fill[i] = 0; g_s[i] = 0.f; g_d[i] = 0.f;
    }
    if (i < 256 * 128) {                      // GEMM1: B[n][k] = W[k][n]
        const int n = i >> 7, k = i & 127;
        const float v = W[(size_t)k * C_MID + n];
        const __nv_bfloat16 h = __float2bfloat16(v);
        g_b1hi[n * PITCH + k] = h;
        g_b1lo[n * PITCH + k] = __float2bfloat16(v - __bfloat162float(h));
    } else if (i < 2 * 256 * 128) {           // GEMM2: B[n][k] = W_fc2[k][n], 2 K-chunks
        const int idx = i - 256 * 128;
        const int k = idx & 255, n = idx >> 8;
        const float v = W2[(size_t)k * H_DIM + n];
        const __nv_bfloat16 h = __float2bfloat16(v);
        const int off = (k >> 7) * 128 * PITCH + n * PITCH + (k & 127);
        g_b2hi[off] = h;
        g_b2lo[off] = __float2bfloat16(v - __bfloat162float(h));
    }
}

// ---------------- CSR build ----------------
__global__ void hist_kernel(const int* __restrict__ ei) {
    const int e = blockIdx.x * blockDim.x + threadIdx.x;
    if (e >= E_TOT) return;
    const int dst = (e < N_EDGES) ? ei[N_EDGES + e] : (e - N_EDGES);
    atomicAdd(&g_count[dst], 1);
}
__global__ void scan1_kernel() {
    __shared__ int sh[SCAN_BLK];
    const int i = blockIdx.x * SCAN_BLK + threadIdx.x;
    const int v = (i < N_NODES) ? g_count[i] : 0;
    sh[threadIdx.x] = v;
    __syncthreads();
    for (int off = 1; off < SCAN_BLK; off <<= 1) {
        const int t = (threadIdx.x >= off) ? sh[threadIdx.x - off] : 0;
        __syncthreads();
        sh[threadIdx.x] += t;
        __syncthreads();
    }
    if (i < N_NODES) g_rowptr[i] = sh[threadIdx.x] - v;
    if (threadIdx.x == SCAN_BLK - 1) g_partial[blockIdx.x] = sh[SCAN_BLK - 1];
}
__global__ void scan2_kernel() {
    __shared__ int sh[128];
    const int t = threadIdx.x;
    const int v = (t < N_SCAN_BLKS) ? g_partial[t] : 0;
    sh[t] = v;
    __syncthreads();
    for (int off = 1; off < 128; off <<= 1) {
        const int u = (t >= off) ? sh[t - off] : 0;
        __syncthreads();
        sh[t] += u;
        __syncthreads();
    }
    if (t < N_SCAN_BLKS) g_partial[t] = sh[t] - v;
}
__global__ void scan3_kernel() {
    const int i = blockIdx.x * blockDim.x + threadIdx.x;
    if (i < N_NODES) g_rowptr[i] += g_partial[i >> 10];
}
__global__ void scatter_kernel(const int* __restrict__ ei) {
    const int e = blockIdx.x * blockDim.x + threadIdx.x;
    if (e >= E_TOT) return;
    int src, dst;
    if (e < N_EDGES) { src = ei[e]; dst = ei[N_EDGES + e]; }
    else             { src = dst = e - N_EDGES; }
    const int pos = g_rowptr[dst] + atomicAdd(&g_fill[dst], 1);
    g_ecol[pos] = src;
}

// ---------------- edge weights: w[e] = exp(lrelu(s[src]+d[dst])), winv[n]=1/sum ----
__global__ __launch_bounds__(256) void weight_kernel()
{
    const int node = blockIdx.x * 8 + (threadIdx.x >> 5);
    const int lane = threadIdx.x & 31;
    if (node >= N_NODES) return;
    const int beg = g_rowptr[node];
    const int cnt = g_count[node];
    const float dterm = g_d[node];
    float wsum = 0.f;
    for (int k = lane; k < cnt; k += 32) {
        const int src = g_ecol[beg + k];
        float e = g_s[src] + dterm;
        e = (e > 0.f) ? e : NEG_SLOPE * e;
        const float w = __expf(e);          // softmax max-shift cancels exactly
        g_w[beg + k] = w;
        wsum += w;
    }
#pragma unroll
    for (int o = 16; o > 0; o >>= 1)
        wsum += __shfl_xor_sync(0xffffffffu, wsum, o);
    if (lane == 0) g_winv[node] = 1.f / wsum;   // cnt >= 1 (self-loop)
}

// ---------------- bf16 3-pass tensor-core GEMM, 128x128 block (verified R8) ------
template <int EPI, int LDA, int KTOT>
__global__ __launch_bounds__(256) void gemm_bf16(
    const float* __restrict__ A,
    const __nv_bfloat16* __restrict__ Bhi, const __nv_bfloat16* __restrict__ Blo,
    const float* __restrict__ bias, float* __restrict__ C,
    const float* __restrict__ v1,   // EPI0: a_src   EPI1: W_out
    const float* __restrict__ v2,   // EPI0: a_dst   EPI1: b_out
    float* __restrict__ outp, int M)
{
    extern __shared__ char smem[];
    __nv_bfloat16* Ahi = reinterpret_cast<__nv_bfloat16*>(smem + SM_SMALL);
    __nv_bfloat16* Alo = Ahi + PLANE;
    __nv_bfloat16* Bhs = Alo + PLANE;
    __nv_bfloat16* Bls = Bhs + PLANE;
    float* sv1 = reinterpret_cast<float*>(smem);
    float* sv2 = reinterpret_cast<float*>(smem + 3072);

    const int tid = threadIdx.x;
    const int lane = tid & 31;
    const int warp = tid >> 5;
    const int warp_m = warp >> 2, warp_n = warp & 3;
    const int row0 = blockIdx.y * 128;
    const int col0 = blockIdx.x * 128;
    const int gq = lane >> 2;
    const int c2 = (lane & 3) * 2;

    if (EPI == 0) {
        if (tid < 128) { sv1[tid] = v1[col0 + tid]; sv2[tid] = v2[col0 + tid]; }
    } else {
#pragma unroll
        for (int i = 0; i < 3; i++) sv1[tid + 256 * i] = v1[tid + 256 * i];
        if (tid < 128) sv2[tid] = bias[tid];
    }

    float acc[4][4][4];
#pragma unroll
    for (int mt = 0; mt < 4; mt++)
#pragma unroll
        for (int nt = 0; nt < 4; nt++)
#pragma unroll
            for (int q = 0; q < 4; q++) acc[mt][nt][q] = 0.f;

    constexpr int NCHUNK = KTOT / 128;
    for (int chunk = 0; chunk < NCHUNK; chunk++) {
        {
            const int r = tid >> 1, h = (tid & 1) * 64;
            const bool ok = (row0 + r) < M;
            const float4* ap = reinterpret_cast<const float4*>(
                A + (size_t)(row0 + r) * LDA + chunk * 128 + h);
#pragma unroll
            for (int j = 0; j < 16; j++) {
                float4 v = make_float4(0.f, 0.f, 0.f, 0.f);
                if (ok) v = ap[j];
                const int off = r * PITCH + h + 4 * j;
                split_store(Ahi, Alo, off, v.x, v.y);
                split_store(Ahi, Alo, off + 2, v.z, v.w);
            }
        }
        {
            const size_t boff = (size_t)(chunk * 128 + col0) * PITCH;
            const float4* sh = reinterpret_cast<const float4*>(Bhi + boff);
            const float4* sl = reinterpret_cast<const float4*>(Blo + boff);
            float4* dh = reinterpret_cast<float4*>(Bhs);
            float4* dl = reinterpret_cast<float4*>(Bls);
            for (int i = tid; i < PLANE / 8; i += 256) { dh[i] = sh[i]; dl[i] = sl[i]; }
        }
        __syncthreads();

#pragma unroll
        for (int ks = 0; ks < 8; ks++) {
            const int kk = ks * 16;
            uint32_t ahi[4][4], alo[4][4];
#pragma unroll
            for (int mt = 0; mt < 4; mt++) {
                const int r = warp_m * 64 + mt * 16 + gq;
                ahi[mt][0] = *reinterpret_cast<const uint32_t*>(&Ahi[r * PITCH + kk + c2]);
                ahi[mt][1] = *reinterpret_cast<const uint32_t*>(&Ahi[(r + 8) * PITCH + kk + c2]);
                ahi[mt][2] = *reinterpret_cast<const uint32_t*>(&Ahi[r * PITCH + kk + c2 + 8]);
                ahi[mt][3] = *reinterpret_cast<const uint32_t*>(&Ahi[(r + 8) * PITCH + kk + c2 + 8]);
                alo[mt][0] = *reinterpret_cast<const uint32_t*>(&Alo[r * PITCH + kk + c2]);
                alo[mt][1] = *reinterpret_cast<const uint32_t*>(&Alo[(r + 8) * PITCH + kk + c2]);
                alo[mt][2] = *reinterpret_cast<const uint32_t*>(&Alo[r * PITCH + kk + c2 + 8]);
                alo[mt][3] = *reinterpret_cast<const uint32_t*>(&Alo[(r + 8) * PITCH + kk + c2 + 8]);
            }
            uint32_t bhi[4][2], blo[4][2];
#pragma unroll
            for (int nt = 0; nt < 4; nt++) {
                const int n = warp_n * 32 + nt * 8 + gq;
                bhi[nt][0] = *reinterpret_cast<const uint32_t*>(&Bhs[n * PITCH + kk + c2]);
                bhi[nt][1] = *reinterpret_cast<const uint32_t*>(&Bhs[n * PITCH + kk + c2 + 8]);
                blo[nt][0] = *reinterpret_cast<const uint32_t*>(&Bls[n * PITCH + kk + c2]);
                blo[nt][1] = *reinterpret_cast<const uint32_t*>(&Bls[n * PITCH + kk + c2 + 8]);
            }
#pragma unroll
            for (int mt = 0; mt < 4; mt++)
#pragma unroll
                for (int nt = 0; nt < 4; nt++) {
                    mma_bf16(acc[mt][nt], ahi[mt], bhi[nt][0], bhi[nt][1]);
                    mma_bf16(acc[mt][nt], ahi[mt], blo[nt][0], blo[nt][1]);
                    mma_bf16(acc[mt][nt], alo[mt], bhi[nt][0], bhi[nt][1]);
                }
        }
        __syncthreads();
    }

    if (EPI == 0) {
#pragma unroll
        for (int mt = 0; mt < 4; mt++) {
            const int r = row0 + warp_m * 64 + mt * 16 + gq;
#pragma unroll
            for (int nt = 0; nt < 4; nt++) {
                const int c = col0 + warp_n * 32 + nt * 8 + c2;
                if (r < M)
                    *reinterpret_cast<float2*>(C + (size_t)r * C_MID + c) =
                        make_float2(acc[mt][nt][0], acc[mt][nt][1]);
                if (r + 8 < M)
                    *reinterpret_cast<float2*>(C + (size_t)(r + 8) * C_MID + c) =
                        make_float2(acc[mt][nt][2], acc[mt][nt][3]);
            }
        }
        float avv[4][2], dvv[4][2];
#pragma unroll
        for (int nt = 0; nt < 4; nt++) {
            const int lc = warp_n * 32 + nt * 8 + c2;
            avv[nt][0] = sv1[lc]; avv[nt][1] = sv1[lc + 1];
            dvv[nt][0] = sv2[lc]; dvv[nt][1] = sv2[lc + 1];
        }
#pragma unroll
        for (int mt = 0; mt < 4; mt++) {
            float ps0 = 0.f, pd0 = 0.f, ps8 = 0.f, pd8 = 0.f;
#pragma unroll
            for (int nt = 0; nt < 4; nt++) {
                ps0 = fmaf(acc[mt][nt][0], avv[nt][0], fmaf(acc[mt][nt][1], avv[nt][1], ps0));
                pd0 = fmaf(acc[mt][nt][0], dvv[nt][0], fmaf(acc[mt][nt][1], dvv[nt][1], pd0));
                ps8 = fmaf(acc[mt][nt][2], avv[nt][0], fmaf(acc[mt][nt][3], avv[nt][1], ps8));
                pd8 = fmaf(acc[mt][nt][2], dvv[nt][0], fmaf(acc[mt][nt][3], dvv[nt][1], pd8));
            }
#pragma unroll
            for (int off = 1; off <= 2; off <<= 1) {
                ps0 += __shfl_xor_sync(0xffffffffu, ps0, off);
                pd0 += __shfl_xor_sync(0xffffffffu, pd0, off);
                ps8 += __shfl_xor_sync(0xffffffffu, ps8, off);
                pd8 += __shfl_xor_sync(0xffffffffu, pd8, off);
            }
            if ((lane & 3) == 0) {
                const int r = row0 + warp_m * 64 + mt * 16 + gq;
                if (r < M)     { atomicAdd(&g_s[r], ps0);     atomicAdd(&g_d[r], pd0); }
                if (r + 8 < M) { atomicAdd(&g_s[r + 8], ps8); atomicAdd(&g_d[r + 8], pd8); }
            }
        }
    } else {
        float bb[4][2];
#pragma unroll
        for (int nt = 0; nt < 4; nt++) {
            const int lc = warp_n * 32 + nt * 8 + c2;
            bb[nt][0] = sv2[lc]; bb[nt][1] = sv2[lc + 1];
        }
#pragma unroll
        for (int mt = 0; mt < 4; mt++)
#pragma unroll
            for (int nt = 0; nt < 4; nt++) {
                acc[mt][nt][0] = fmaxf(acc[mt][nt][0] + bb[nt][0], 0.f);
                acc[mt][nt][1] = fmaxf(acc[mt][nt][1] + bb[nt][1], 0.f);
                acc[mt][nt][2] = fmaxf(acc[mt][nt][2] + bb[nt][0], 0.f);
                acc[mt][nt][3] = fmaxf(acc[mt][nt][3] + bb[nt][1], 0.f);
            }
        float* red = reinterpret_cast<float*>(smem + SM_SMALL);
#pragma unroll
        for (int o = 0; o < O_DIM; o++) {
            float wv0[4], wv1[4];
#pragma unroll
            for (int nt = 0; nt < 4; nt++) {
                const int lc = warp_n * 32 + nt * 8 + c2;
                wv0[nt] = sv1[lc * O_DIM + o];
                wv1[nt] = sv1[(lc + 1) * O_DIM + o];
            }
#pragma unroll
            for (int mt = 0; mt < 4; mt++) {
                float p0 = 0.f, p8 = 0.f;
#pragma unroll
                for (int nt = 0; nt < 4; nt++) {
                    p0 = fmaf(acc[mt][nt][0], wv0[nt], fmaf(acc[mt][nt][1], wv1[nt], p0));
                    p8 = fmaf(acc[mt][nt][2], wv0[nt], fmaf(acc[mt][nt][3], wv1[nt], p8));
                }
#pragma unroll
                for (int off = 1; off <= 2; off <<= 1) {
                    p0 += __shfl_xor_sync(0xffffffffu, p0, off);
                    p8 += __shfl_xor_sync(0xffffffffu, p8, off);
                }
                if ((lane & 3) == 0) {
                    const int rl = warp_m * 64 + mt * 16 + gq;
                    red[rl * 25 + warp_n * 6 + o] = p0;
                    red[(rl + 8) * 25 + warp_n * 6 + o] = p8;
                }
            }
        }
        __syncthreads();
        if (tid < 128) {
            const int r = row0 + tid;
            if (r < M) {
#pragma unroll
                for (int o = 0; o < O_DIM; o++) {
                    const float s = red[tid * 25 + o] + red[tid * 25 + 6 + o]
                                  + red[tid * 25 + 12 + o] + red[tid * 25 + 18 + o];
                    outp[(size_t)r * O_DIM + o] = s + v2[o];
                }
            }
        }
    }
}

// ---------------- CSR aggregate over one 128-col half (4-way unrolled MLP) -------
template <int HALF>
__global__ __launch_bounds__(256) void agg_half_kernel(const float* __restrict__ bias)
{
    const int node = blockIdx.x * 8 + (threadIdx.x >> 5);
    const int t    = threadIdx.x & 31;
    if (node >= N_NODES) return;

    const int beg = g_rowptr[node];
    const int cnt = g_count[node];
    const float* base = g_xw + (size_t)HALF * 128 + t * 4;

    float4 a0 = make_float4(0.f, 0.f, 0.f, 0.f);
    float4 a1 = a0, a2 = a0, a3 = a0;

    int k = 0;
    for (; k + 4 <= cnt; k += 4) {
        const int s0 = g_ecol[beg + k];
        const int s1 = g_ecol[beg + k + 1];
        const int s2 = g_ecol[beg + k + 2];
        const int s3 = g_ecol[beg + k + 3];
        const float w0 = g_w[beg + k];
        const float w1 = g_w[beg + k + 1];
        const float w2 = g_w[beg + k + 2];
        const float w3 = g_w[beg + k + 3];
        const float4 v0 = *reinterpret_cast<const float4*>(base + (size_t)s0 * C_MID);
        const float4 v1 = *reinterpret_cast<const float4*>(base + (size_t)s1 * C_MID);
        const float4 v2 = *reinterpret_cast<const float4*>(base + (size_t)s2 * C_MID);
        const float4 v3 = *reinterpret_cast<const float4*>(base + (size_t)s3 * C_MID);
        a0.x = fmaf(w0, v0.x, a0.x); a0.y = fmaf(w0, v0.y, a0.y);
        a0.z = fmaf(w0, v0.z, a0.z); a0.w = fmaf(w0, v0.w, a0.w);
        a1.x = fmaf(w1, v1.x, a1.x); a1.y = fmaf(w1, v1.y, a1.y);
        a1.z = fmaf(w1, v1.z, a1.z); a1.w = fmaf(w1, v1.w, a1.w);
        a2.x = fmaf(w2, v2.x, a2.x); a2.y = fmaf(w2, v2.y, a2.y);
        a2.z = fmaf(w2, v2.z, a2.z); a2.w = fmaf(w2, v2.w, a2.w);
        a3.x = fmaf(w3, v3.x, a3.x); a3.y = fmaf(w3, v3.y, a3.y);
        a3.z = fmaf(w3, v3.z, a3.z); a3.w = fmaf(w3, v3.w, a3.w);
    }
    for (; k < cnt; k++) {
        const int s0 = g_ecol[beg + k];
        const float w0 = g_w[beg + k];
        const float4 v0 = *reinterpret_cast<const float4*>(base + (size_t)s0 * C_MID);
        a0.x = fmaf(w0, v0.x, a0.x); a0.y = fmaf(w0, v0.y, a0.y);
        a0.z = fmaf(w0, v0.z, a0.z); a0.w = fmaf(w0, v0.w, a0.w);
    }
    float4 acc;
    acc.x = (a0.x + a1.x) + (a2.x + a3.x);
    acc.y = (a0.y + a1.y) + (a2.y + a3.y);
    acc.z = (a0.z + a1.z) + (a2.z + a3.z);
    acc.w = (a0.w + a1.w) + (a2.w + a3.w);

    const float inv = g_winv[node];
    const float4 bb = reinterpret_cast<const float4*>(bias)[HALF * 32 + t];
    float4 o;
    o.x = fmaxf(fmaf(acc.x, inv, bb.x), 0.f);
    o.y = fmaxf(fmaf(acc.y, inv, bb.y), 0.f);
    o.z = fmaxf(fmaf(acc.z, inv, bb.z), 0.f);
    o.w = fmaxf(fmaf(acc.w, inv, bb.w), 0.f);
    *reinterpret_cast<float4*>(
        g_gat + (size_t)node * C_MID + HALF * 128 + t * 4) = o;
}

// ---------------- launch ----------------
extern "C" void kernel_launch(void* const* d_in, const int* in_sizes, int n_in,
                              void* d_out, int out_size)
{
    const float* x      = (const float*)d_in[0];
    const int*   ei     = (const int*)  d_in[1];
    const float* W      = (const float*)d_in[2];
    const float* a_src  = (const float*)d_in[3];
    const float* a_dst  = (const float*)d_in[4];
    const float* b      = (const float*)d_in[5];
    const float* W_fc2  = (const float*)d_in[6];
    const float* b_fc2  = (const float*)d_in[7];
    const float* W_out  = (const float*)d_in[8];
    const float* b_out  = (const float*)d_in[9];
    float* out = (float*)d_out;

    float *xw, *gat;
    __nv_bfloat16 *b1h, *b1l, *b2h, *b2l;
    cudaGetSymbolAddress((void**)&xw,  g_xw);
    cudaGetSymbolAddress((void**)&gat, g_gat);
    cudaGetSymbolAddress((void**)&b1h, g_b1hi);
    cudaGetSymbolAddress((void**)&b1l, g_b1lo);
    cudaGetSymbolAddress((void**)&b2h, g_b2hi);
    cudaGetSymbolAddress((void**)&b2l, g_b2lo);

    static bool inited = false;
    if (!inited) {
        cudaFuncSetAttribute((const void*)gemm_bf16<0, F_IN, 128>,
                             cudaFuncAttributeMaxDynamicSharedMemorySize, SM_TOTAL);
        cudaFuncSetAttribute((const void*)gemm_bf16<1, C_MID, 256>,
                             cudaFuncAttributeMaxDynamicSharedMemorySize, SM_TOTAL);
        inited = true;
    }

    const int nblk = (N_NODES + 127) / 128;   // 782

    // 1) fused init + B prep
    initprep_kernel<<<(N_NODES + 255) / 256, 256>>>(W, W_fc2);

    // 2) CSR build
    hist_kernel<<<(E_TOT + 255) / 256, 256>>>(ei);
    scan1_kernel<<<N_SCAN_BLKS, SCAN_BLK>>>();
    scan2_kernel<<<1, 128>>>();
    scan3_kernel<<<(N_NODES + 255) / 256, 256>>>();
    scatter_kernel<<<(E_TOT + 255) / 256, 256>>>(ei);

    // 3) xw = x @ W (bf16 3-pass tensor cores) + fused s/d dots
    {
        dim3 grid(C_MID / 128, nblk);
        gemm_bf16<0, F_IN, 128><<<grid, 256, SM_TOTAL>>>(
            x, b1h, b1l, nullptr, xw, a_src, a_dst, nullptr, N_NODES);
    }

    // 4) edge softmax weights, then two L2-resident half-column gather passes
    weight_kernel<<<(N_NODES + 7) / 8, 256>>>();
    agg_half_kernel<0><<<(N_NODES + 7) / 8, 256>>>(b);
    agg_half_kernel<1><<<(N_NODES + 7) / 8, 256>>>(b);

    // 5+6) out = relu(h2 @ W_fc2 + b_fc2) @ W_out + b_out (bf16 3-pass, fused)
    {
        dim3 grid(1, nblk);
        gemm_bf16<1, C_MID, 256><<<grid, 256, SM_TOTAL>>>(
            gat, b2h, b2l, b_fc2, nullptr, W_out, b_out, out, N_NODES);
    }
}

// round 12
// speedup vs baseline: 1.5867x; 1.0439x over previous
#include <cuda_runtime.h>
#include <cuda_bf16.h>
#include <cstdint>

#define N_NODES 100000
#define N_EDGES 800000
#define F_IN    128
#define C_MID   256
#define H_DIM   128
#define O_DIM   6
#define NEG_SLOPE 0.2f

#define E_TOT (N_EDGES + N_NODES)
#define SCAN_BLK 1024
#define N_SCAN_BLKS ((N_NODES + SCAN_BLK - 1) / SCAN_BLK)   // 98

#define PITCH 136                        // bf16 elems per smem row (conflict-free)
#define PLANE (128 * PITCH)              // elems per plane
#define SM_SMALL 4096                    // bytes reserved for vectors
#define SM_TOTAL (SM_SMALL + 4 * PLANE * 2)   // 143360 bytes

// ---------------- device scratch ----------------
__device__ float g_xw[(size_t)N_NODES * C_MID];
__device__ float g_gat[(size_t)N_NODES * C_MID];
__device__ float g_s[N_NODES];
__device__ float g_d[N_NODES];
__device__ float g_w[E_TOT];
__device__ float g_winv[N_NODES];
__device__ int   g_count[N_NODES];
__device__ int   g_rowptr[N_NODES];
__device__ int   g_fill[N_NODES];
__device__ int   g_partial[N_SCAN_BLKS];
__device__ int   g_scan_done;
__device__ int   g_ecol[E_TOT];
// pre-split, pre-transposed bf16 B-operand planes ([N][PITCH] row-major, K contig)
__device__ __nv_bfloat16 g_b1hi[256 * PITCH];
__device__ __nv_bfloat16 g_b1lo[256 * PITCH];
__device__ __nv_bfloat16 g_b2hi[2 * 128 * PITCH];
__device__ __nv_bfloat16 g_b2lo[2 * 128 * PITCH];

// ---------------- helpers ----------------
__device__ __forceinline__ void mma_bf16(float* c, const uint32_t* a, uint32_t b0, uint32_t b1) {
    asm volatile(
        "mma.sync.aligned.m16n8k16.row.col.f32.bf16.bf16.f32 "
        "{%0,%1,%2,%3}, {%4,%5,%6,%7}, {%8,%9}, {%0,%1,%2,%3};"
        : "+f"(c[0]), "+f"(c[1]), "+f"(c[2]), "+f"(c[3])
        : "r"(a[0]), "r"(a[1]), "r"(a[2]), "r"(a[3]), "r"(b0), "r"(b1));
}

__device__ __forceinline__ void split_store(__nv_bfloat16* hi, __nv_bfloat16* lo,
                                            int off, float x, float y) {
    const __nv_bfloat16 hx = __float2bfloat16(x), hy = __float2bfloat16(y);
    const float rx = x - __bfloat162float(hx), ry = y - __bfloat162float(hy);
    *reinterpret_cast<__nv_bfloat162*>(hi + off) = __nv_bfloat162{hx, hy};
    *reinterpret_cast<__nv_bfloat162*>(lo + off) =
        __nv_bfloat162{__float2bfloat16(rx), __float2bfloat16(ry)};
}

// ---------------- init ----------------
__global__ void init_kernel() {
    const int i = blockIdx.x * blockDim.x + threadIdx.x;
    if (i < N_NODES) {
        g_count[i] = 0; g_fill[i] = 0; g_s[i] = 0.f; g_d[i] = 0.f;
    }
    if (i == 0) g_scan_done = 0;
}

// ---------------- prep: split + transpose B operands once ----------------
__global__ void prep_kernel(const float* __restrict__ W, const float* __restrict__ W2) {
    int idx = blockIdx.x * 256 + threadIdx.x;
    if (idx < 256 * 128) {                    // GEMM1: B[n][k] = W[k][n]
        const int n = idx >> 7, k = idx & 127;
        const float v = W[(size_t)k * C_MID + n];
        const __nv_bfloat16 h = __float2bfloat16(v);
        g_b1hi[n * PITCH + k] = h;
        g_b1lo[n * PITCH + k] = __float2bfloat16(v - __bfloat162float(h));
    } else {                                  // GEMM2: B[n][k] = W_fc2[k][n], 2 K-chunks
        idx -= 256 * 128;
        const int k = idx & 255, n = idx >> 8;
        const float v = W2[(size_t)k * H_DIM + n];
        const __nv_bfloat16 h = __float2bfloat16(v);
        const int off = (k >> 7) * 128 * PITCH + n * PITCH + (k & 127);
        g_b2hi[off] = h;
        g_b2lo[off] = __float2bfloat16(v - __bfloat162float(h));
    }
}

// ---------------- CSR build ----------------
__global__ void hist_kernel(const int* __restrict__ ei) {
    const int e = blockIdx.x * blockDim.x + threadIdx.x;
    if (e >= E_TOT) return;
    const int dst = (e < N_EDGES) ? ei[N_EDGES + e] : (e - N_EDGES);
    atomicAdd(&g_count[dst], 1);
}

// fused 3-stage exclusive scan; 98 blocks <= 148 SMs so all are co-resident
// and an atomic-counter spin is a safe grid-wide barrier.
__global__ void scan_fused_kernel() {
    __shared__ int sh[SCAN_BLK];
    __shared__ int base;
    const int i = blockIdx.x * SCAN_BLK + threadIdx.x;
    const int v = (i < N_NODES) ? g_count[i] : 0;
    sh[threadIdx.x] = v;
    __syncthreads();
    for (int off = 1; off < SCAN_BLK; off <<= 1) {
        const int t = (threadIdx.x >= off) ? sh[threadIdx.x - off] : 0;
        __syncthreads();
        sh[threadIdx.x] += t;
        __syncthreads();
    }
    const int incl = sh[threadIdx.x];
    if (threadIdx.x == SCAN_BLK - 1) {
        g_partial[blockIdx.x] = incl;         // block total
        __threadfence();
        atomicAdd(&g_scan_done, 1);
    }
    if (threadIdx.x == 0) {
        while (atomicAdd(&g_scan_done, 0) < N_SCAN_BLKS) {}
        int acc = 0;
        for (int bb = 0; bb < blockIdx.x; bb++) acc += g_partial[bb];
        base = acc;
    }
    __syncthreads();
    if (i < N_NODES) g_rowptr[i] = base + incl - v;   // exclusive global scan
}

__global__ void scatter_kernel(const int* __restrict__ ei) {
    const int e = blockIdx.x * blockDim.x + threadIdx.x;
    if (e >= E_TOT) return;
    int src, dst;
    if (e < N_EDGES) { src = ei[e]; dst = ei[N_EDGES + e]; }
    else             { src = dst = e - N_EDGES; }
    const int pos = g_rowptr[dst] + atomicAdd(&g_fill[dst], 1);
    g_ecol[pos] = src;
}

// ---------------- edge weights: w[e] = exp(lrelu(s[src]+d[dst])), winv[n]=1/sum ----
__global__ __launch_bounds__(256) void weight_kernel()
{
    const int node = blockIdx.x * 8 + (threadIdx.x >> 5);
    const int lane = threadIdx.x & 31;
    if (node >= N_NODES) return;
    const int beg = g_rowptr[node];
    const int cnt = g_count[node];
    const float dterm = g_d[node];
    float wsum = 0.f;
    for (int k = lane; k < cnt; k += 32) {
        const int src = g_ecol[beg + k];
        float e = g_s[src] + dterm;
        e = (e > 0.f) ? e : NEG_SLOPE * e;
        const float w = __expf(e);          // softmax max-shift cancels exactly
        g_w[beg + k] = w;
        wsum += w;
    }
#pragma unroll
    for (int o = 16; o > 0; o >>= 1)
        wsum += __shfl_xor_sync(0xffffffffu, wsum, o);
    if (lane == 0) g_winv[node] = 1.f / wsum;   // cnt >= 1 (self-loop)
}

// ---------------- bf16 3-pass tensor-core GEMM, 128x128 block (verified R8) ------
// EPI 0: C=xw store + fused a_src/a_dst dots -> g_s/g_d (atomic)
// EPI 1: relu(acc+bias) then fused 128->6 GEMM with W_out -> outp (no C store)
template <int EPI, int LDA, int KTOT>
__global__ __launch_bounds__(256) void gemm_bf16(
    const float* __restrict__ A,
    const __nv_bfloat16* __restrict__ Bhi, const __nv_bfloat16* __restrict__ Blo,
    const float* __restrict__ bias, float* __restrict__ C,
    const float* __restrict__ v1,   // EPI0: a_src   EPI1: W_out
    const float* __restrict__ v2,   // EPI0: a_dst   EPI1: b_out
    float* __restrict__ outp, int M)
{
    extern __shared__ char smem[];
    __nv_bfloat16* Ahi = reinterpret_cast<__nv_bfloat16*>(smem + SM_SMALL);
    __nv_bfloat16* Alo = Ahi + PLANE;
    __nv_bfloat16* Bhs = Alo + PLANE;
    __nv_bfloat16* Bls = Bhs + PLANE;
    float* sv1 = reinterpret_cast<float*>(smem);
    float* sv2 = reinterpret_cast<float*>(smem + 3072);

    const int tid = threadIdx.x;
    const int lane = tid & 31;
    const int warp = tid >> 5;
    const int warp_m = warp >> 2, warp_n = warp & 3;
    const int row0 = blockIdx.y * 128;
    const int col0 = blockIdx.x * 128;
    const int gq = lane >> 2;
    const int c2 = (lane & 3) * 2;

    if (EPI == 0) {
        if (tid < 128) { sv1[tid] = v1[col0 + tid]; sv2[tid] = v2[col0 + tid]; }
    } else {
#pragma unroll
        for (int i = 0; i < 3; i++) sv1[tid + 256 * i] = v1[tid + 256 * i];
        if (tid < 128) sv2[tid] = bias[tid];
    }

    float acc[4][4][4];
#pragma unroll
    for (int mt = 0; mt < 4; mt++)
#pragma unroll
        for (int nt = 0; nt < 4; nt++)
#pragma unroll
            for (int q = 0; q < 4; q++) acc[mt][nt][q] = 0.f;

    constexpr int NCHUNK = KTOT / 128;
    for (int chunk = 0; chunk < NCHUNK; chunk++) {
        // ---- stage A: split fp32 -> hi/lo bf16 ----
        {
            const int r = tid >> 1, h = (tid & 1) * 64;
            const bool ok = (row0 + r) < M;
            const float4* ap = reinterpret_cast<const float4*>(
                A + (size_t)(row0 + r) * LDA + chunk * 128 + h);
#pragma unroll
            for (int j = 0; j < 16; j++) {
                float4 v = make_float4(0.f, 0.f, 0.f, 0.f);
                if (ok) v = ap[j];
                const int off = r * PITCH + h + 4 * j;
                split_store(Ahi, Alo, off, v.x, v.y);
                split_store(Ahi, Alo, off + 2, v.z, v.w);
            }
        }
        // ---- stage B: plain copy of pre-split planes ----
        {
            const size_t boff = (size_t)(chunk * 128 + col0) * PITCH;
            const float4* sh = reinterpret_cast<const float4*>(Bhi + boff);
            const float4* sl = reinterpret_cast<const float4*>(Blo + boff);
            float4* dh = reinterpret_cast<float4*>(Bhs);
            float4* dl = reinterpret_cast<float4*>(Bls);
            for (int i = tid; i < PLANE / 8; i += 256) { dh[i] = sh[i]; dl[i] = sl[i]; }
        }
        __syncthreads();

        // ---- mainloop: 8 k-steps of 16, 3 passes, no syncs ----
#pragma unroll
        for (int ks = 0; ks < 8; ks++) {
            const int kk = ks * 16;
            uint32_t ahi[4][4], alo[4][4];
#pragma unroll
            for (int mt = 0; mt < 4; mt++) {
                const int r = warp_m * 64 + mt * 16 + gq;
                ahi[mt][0] = *reinterpret_cast<const uint32_t*>(&Ahi[r * PITCH + kk + c2]);
                ahi[mt][1] = *reinterpret_cast<const uint32_t*>(&Ahi[(r + 8) * PITCH + kk + c2]);
                ahi[mt][2] = *reinterpret_cast<const uint32_t*>(&Ahi[r * PITCH + kk + c2 + 8]);
                ahi[mt][3] = *reinterpret_cast<const uint32_t*>(&Ahi[(r + 8) * PITCH + kk + c2 + 8]);
                alo[mt][0] = *reinterpret_cast<const uint32_t*>(&Alo[r * PITCH + kk + c2]);
                alo[mt][1] = *reinterpret_cast<const uint32_t*>(&Alo[(r + 8) * PITCH + kk + c2]);
                alo[mt][2] = *reinterpret_cast<const uint32_t*>(&Alo[r * PITCH + kk + c2 + 8]);
                alo[mt][3] = *reinterpret_cast<const uint32_t*>(&Alo[(r + 8) * PITCH + kk + c2 + 8]);
            }
            uint32_t bhi[4][2], blo[4][2];
#pragma unroll
            for (int nt = 0; nt < 4; nt++) {
                const int n = warp_n * 32 + nt * 8 + gq;
                bhi[nt][0] = *reinterpret_cast<const uint32_t*>(&Bhs[n * PITCH + kk + c2]);
                bhi[nt][1] = *reinterpret_cast<const uint32_t*>(&Bhs[n * PITCH + kk + c2 + 8]);
                blo[nt][0] = *reinterpret_cast<const uint32_t*>(&Bls[n * PITCH + kk + c2]);
                blo[nt][1] = *reinterpret_cast<const uint32_t*>(&Bls[n * PITCH + kk + c2 + 8]);
            }
#pragma unroll
            for (int mt = 0; mt < 4; mt++)
#pragma unroll
                for (int nt = 0; nt < 4; nt++) {
                    mma_bf16(acc[mt][nt], ahi[mt], bhi[nt][0], bhi[nt][1]);
                    mma_bf16(acc[mt][nt], ahi[mt], blo[nt][0], blo[nt][1]);
                    mma_bf16(acc[mt][nt], alo[mt], bhi[nt][0], bhi[nt][1]);
                }
        }
        __syncthreads();
    }

    if (EPI == 0) {
        // ---- store C + fused a_src/a_dst dots ----
#pragma unroll
        for (int mt = 0; mt < 4; mt++) {
            const int r = row0 + warp_m * 64 + mt * 16 + gq;
#pragma unroll
            for (int nt = 0; nt < 4; nt++) {
                const int c = col0 + warp_n * 32 + nt * 8 + c2;
                if (r < M)
                    *reinterpret_cast<float2*>(C + (size_t)r * C_MID + c) =
                        make_float2(acc[mt][nt][0], acc[mt][nt][1]);
                if (r + 8 < M)
                    *reinterpret_cast<float2*>(C + (size_t)(r + 8) * C_MID + c) =
                        make_float2(acc[mt][nt][2], acc[mt][nt][3]);
            }
        }
        float avv[4][2], dvv[4][2];
#pragma unroll
        for (int nt = 0; nt < 4; nt++) {
            const int lc = warp_n * 32 + nt * 8 + c2;
            avv[nt][0] = sv1[lc]; avv[nt][1] = sv1[lc + 1];
            dvv[nt][0] = sv2[lc]; dvv[nt][1] = sv2[lc + 1];
        }
#pragma unroll
        for (int mt = 0; mt < 4; mt++) {
            float ps0 = 0.f, pd0 = 0.f, ps8 = 0.f, pd8 = 0.f;
#pragma unroll
            for (int nt = 0; nt < 4; nt++) {
                ps0 = fmaf(acc[mt][nt][0], avv[nt][0], fmaf(acc[mt][nt][1], avv[nt][1], ps0));
                pd0 = fmaf(acc[mt][nt][0], dvv[nt][0], fmaf(acc[mt][nt][1], dvv[nt][1], pd0));
                ps8 = fmaf(acc[mt][nt][2], avv[nt][0], fmaf(acc[mt][nt][3], avv[nt][1], ps8));
                pd8 = fmaf(acc[mt][nt][2], dvv[nt][0], fmaf(acc[mt][nt][3], dvv[nt][1], pd8));
            }
#pragma unroll
            for (int off = 1; off <= 2; off <<= 1) {
                ps0 += __shfl_xor_sync(0xffffffffu, ps0, off);
                pd0 += __shfl_xor_sync(0xffffffffu, pd0, off);
                ps8 += __shfl_xor_sync(0xffffffffu, ps8, off);
                pd8 += __shfl_xor_sync(0xffffffffu, pd8, off);
            }
            if ((lane & 3) == 0) {
                const int r = row0 + warp_m * 64 + mt * 16 + gq;
                if (r < M)     { atomicAdd(&g_s[r], ps0);     atomicAdd(&g_d[r], pd0); }
                if (r + 8 < M) { atomicAdd(&g_s[r + 8], ps8); atomicAdd(&g_d[r + 8], pd8); }
            }
        }
    } else {
        // ---- EPI1: h = relu(acc + bias); out = h @ W_out + b_out ----
        float bb[4][2];
#pragma unroll
        for (int nt = 0; nt < 4; nt++) {
            const int lc = warp_n * 32 + nt * 8 + c2;
            bb[nt][0] = sv2[lc]; bb[nt][1] = sv2[lc + 1];
        }
#pragma unroll
        for (int mt = 0; mt < 4; mt++)
#pragma unroll
            for (int nt = 0; nt < 4; nt++) {
                acc[mt][nt][0] = fmaxf(acc[mt][nt][0] + bb[nt][0], 0.f);
                acc[mt][nt][1] = fmaxf(acc[mt][nt][1] + bb[nt][1], 0.f);
                acc[mt][nt][2] = fmaxf(acc[mt][nt][2] + bb[nt][0], 0.f);
                acc[mt][nt][3] = fmaxf(acc[mt][nt][3] + bb[nt][1], 0.f);
            }
        float* red = reinterpret_cast<float*>(smem + SM_SMALL);   // [128][25]
#pragma unroll
        for (int o = 0; o < O_DIM; o++) {
            float wv0[4], wv1[4];
#pragma unroll
            for (int nt = 0; nt < 4; nt++) {
                const int lc = warp_n * 32 + nt * 8 + c2;
                wv0[nt] = sv1[lc * O_DIM + o];
                wv1[nt] = sv1[(lc + 1) * O_DIM + o];
            }
#pragma unroll
            for (int mt = 0; mt < 4; mt++) {
                float p0 = 0.f, p8 = 0.f;
#pragma unroll
                for (int nt = 0; nt < 4; nt++) {
                    p0 = fmaf(acc[mt][nt][0], wv0[nt], fmaf(acc[mt][nt][1], wv1[nt], p0));
                    p8 = fmaf(acc[mt][nt][2], wv0[nt], fmaf(acc[mt][nt][3], wv1[nt], p8));
                }
#pragma unroll
                for (int off = 1; off <= 2; off <<= 1) {
                    p0 += __shfl_xor_sync(0xffffffffu, p0, off);
                    p8 += __shfl_xor_sync(0xffffffffu, p8, off);
                }
                if ((lane & 3) == 0) {
                    const int rl = warp_m * 64 + mt * 16 + gq;
                    red[rl * 25 + warp_n * 6 + o] = p0;
                    red[(rl + 8) * 25 + warp_n * 6 + o] = p8;
                }
            }
        }
        __syncthreads();
        if (tid < 128) {
            const int r = row0 + tid;
            if (r < M) {
#pragma unroll
                for (int o = 0; o < O_DIM; o++) {
                    const float s = red[tid * 25 + o] + red[tid * 25 + 6 + o]
                                  + red[tid * 25 + 12 + o] + red[tid * 25 + 18 + o];
                    outp[(size_t)r * O_DIM + o] = s + v2[o];
                }
            }
        }
    }
}

// ---------------- CSR aggregate over one 128-col half (R8 shape, untouched) ------
template <int HALF>
__global__ __launch_bounds__(256) void agg_half_kernel(const float* __restrict__ bias)
{
    const int node = blockIdx.x * 8 + (threadIdx.x >> 5);
    const int t    = threadIdx.x & 31;
    if (node >= N_NODES) return;

    const int beg = g_rowptr[node];
    const int cnt = g_count[node];

    float4 acc = make_float4(0.f, 0.f, 0.f, 0.f);
    for (int k = 0; k < cnt; k++) {
        const int src = g_ecol[beg + k];
        const float w = g_w[beg + k];
        const float4 v = *reinterpret_cast<const float4*>(
            g_xw + (size_t)src * C_MID + HALF * 128 + t * 4);
        acc.x = fmaf(w, v.x, acc.x);
        acc.y = fmaf(w, v.y, acc.y);
        acc.z = fmaf(w, v.z, acc.z);
        acc.w = fmaf(w, v.w, acc.w);
    }

    const float inv = g_winv[node];
    const float4 bb = reinterpret_cast<const float4*>(bias)[HALF * 32 + t];
    float4 o;
    o.x = fmaxf(fmaf(acc.x, inv, bb.x), 0.f);
    o.y = fmaxf(fmaf(acc.y, inv, bb.y), 0.f);
    o.z = fmaxf(fmaf(acc.z, inv, bb.z), 0.f);
    o.w = fmaxf(fmaf(acc.w, inv, bb.w), 0.f);
    *reinterpret_cast<float4*>(
        g_gat + (size_t)node * C_MID + HALF * 128 + t * 4) = o;
}

// ---------------- launch ----------------
extern "C" void kernel_launch(void* const* d_in, const int* in_sizes, int n_in,
                              void* d_out, int out_size)
{
    const float* x      = (const float*)d_in[0];
    const int*   ei     = (const int*)  d_in[1];
    const float* W      = (const float*)d_in[2];
    const float* a_src  = (const float*)d_in[3];
    const float* a_dst  = (const float*)d_in[4];
    const float* b      = (const float*)d_in[5];
    const float* W_fc2  = (const float*)d_in[6];
    const float* b_fc2  = (const float*)d_in[7];
    const float* W_out  = (const float*)d_in[8];
    const float* b_out  = (const float*)d_in[9];
    float* out = (float*)d_out;

    float *xw, *gat;
    __nv_bfloat16 *b1h, *b1l, *b2h, *b2l;
    cudaGetSymbolAddress((void**)&xw,  g_xw);
    cudaGetSymbolAddress((void**)&gat, g_gat);
    cudaGetSymbolAddress((void**)&b1h, g_b1hi);
    cudaGetSymbolAddress((void**)&b1l, g_b1lo);
    cudaGetSymbolAddress((void**)&b2h, g_b2hi);
    cudaGetSymbolAddress((void**)&b2l, g_b2lo);

    static bool inited = false;
    if (!inited) {
        cudaFuncSetAttribute((const void*)gemm_bf16<0, F_IN, 128>,
                             cudaFuncAttributeMaxDynamicSharedMemorySize, SM_TOTAL);
        cudaFuncSetAttribute((const void*)gemm_bf16<1, C_MID, 256>,
                             cudaFuncAttributeMaxDynamicSharedMemorySize, SM_TOTAL);
        inited = true;
    }

    const int nblk = (N_NODES + 127) / 128;   // 782

    // 1) init + B prep (separate, as in R8)
    init_kernel<<<(N_NODES + 255) / 256, 256>>>();
    prep_kernel<<<256, 256>>>(W, W_fc2);

    // 2) CSR build (scan fused into one grid-resident kernel)
    hist_kernel<<<(E_TOT + 255) / 256, 256>>>(ei);
    scan_fused_kernel<<<N_SCAN_BLKS, SCAN_BLK>>>();
    scatter_kernel<<<(E_TOT + 255) / 256, 256>>>(ei);

    // 3) xw = x @ W (bf16 3-pass tensor cores) + fused s/d dots
    {
        dim3 grid(C_MID / 128, nblk);
        gemm_bf16<0, F_IN, 128><<<grid, 256, SM_TOTAL>>>(
            x, b1h, b1l, nullptr, xw, a_src, a_dst, nullptr, N_NODES);
    }

    // 4) edge softmax weights, then two L2-resident half-column gather passes
    weight_kernel<<<(N_NODES + 7) / 8, 256>>>();
    agg_half_kernel<0><<<(N_NODES + 7) / 8, 256>>>(b);
    agg_half_kernel<1><<<(N_NODES + 7) / 8, 256>>>(b);

    // 5+6) out = relu(h2 @ W_fc2 + b_fc2) @ W_out + b_out (bf16 3-pass, fused)
    {
        dim3 grid(1, nblk);
        gemm_bf16<1, C_MID, 256><<<grid, 256, SM_TOTAL>>>(
            gat, b2h, b2l, b_fc2, nullptr, W_out, b_out, out, N_NODES);
    }
}

// round 14
// speedup vs baseline: 1.6330x; 1.0292x over previous
#include <cuda_runtime.h>
#include <cuda_bf16.h>
#include <cstdint>

#define N_NODES 100000
#define N_EDGES 800000
#define F_IN    128
#define C_MID   256
#define H_DIM   128
#define O_DIM   6
#define NEG_SLOPE 0.2f

#define E_TOT (N_EDGES + N_NODES)
#define SCAN_BLK 1024
#define N_SCAN_BLKS ((N_NODES + SCAN_BLK - 1) / SCAN_BLK)   // 98

#define PITCH 136                        // bf16 elems per smem row (conflict-free)
#define PLANE (128 * PITCH)              // elems per plane
#define SM_SMALL 4096                    // bytes reserved for vectors
#define SM_TOTAL (SM_SMALL + 4 * PLANE * 2)   // 143360 bytes

// ---------------- device scratch ----------------
__device__ float g_xw[(size_t)N_NODES * C_MID];
__device__ float g_gat[(size_t)N_NODES * C_MID];
__device__ float g_s[N_NODES];
__device__ float g_d[N_NODES];
__device__ float g_w[E_TOT];
__device__ float g_winv[N_NODES];
__device__ int   g_count[N_NODES];
__device__ int   g_rowptr[N_NODES];
__device__ int   g_fill[N_NODES];
__device__ int   g_partial[N_SCAN_BLKS];
__device__ int   g_ecol[E_TOT];
// pre-split, pre-transposed bf16 B-operand planes ([N][PITCH] row-major, K contig)
__device__ __nv_bfloat16 g_b1hi[256 * PITCH];
__device__ __nv_bfloat16 g_b1lo[256 * PITCH];
__device__ __nv_bfloat16 g_b2hi[2 * 128 * PITCH];
__device__ __nv_bfloat16 g_b2lo[2 * 128 * PITCH];

// ---------------- helpers ----------------
__device__ __forceinline__ void mma_bf16(float* c, const uint32_t* a, uint32_t b0, uint32_t b1) {
    asm volatile(
        "mma.sync.aligned.m16n8k16.row.col.f32.bf16.bf16.f32 "
        "{%0,%1,%2,%3}, {%4,%5,%6,%7}, {%8,%9}, {%0,%1,%2,%3};"
        : "+f"(c[0]), "+f"(c[1]), "+f"(c[2]), "+f"(c[3])
        : "r"(a[0]), "r"(a[1]), "r"(a[2]), "r"(a[3]), "r"(b0), "r"(b1));
}

__device__ __forceinline__ void split_store(__nv_bfloat16* hi, __nv_bfloat16* lo,
                                            int off, float x, float y) {
    const __nv_bfloat16 hx = __float2bfloat16(x), hy = __float2bfloat16(y);
    const float rx = x - __bfloat162float(hx), ry = y - __bfloat162float(hy);
    *reinterpret_cast<__nv_bfloat162*>(hi + off) = __nv_bfloat162{hx, hy};
    *reinterpret_cast<__nv_bfloat162*>(lo + off) =
        __nv_bfloat162{__float2bfloat16(rx), __float2bfloat16(ry)};
}

// ---------------- init ----------------
__global__ void init_kernel() {
    const int i = blockIdx.x * blockDim.x + threadIdx.x;
    if (i < N_NODES) {
        g_count[i] = 0; g_fill[i] = 0; g_s[i] = 0.f; g_d[i] = 0.f;
    }
}

// ---------------- prep: split + transpose B operands once ----------------
__global__ void prep_kernel(const float* __restrict__ W, const float* __restrict__ W2) {
    int idx = blockIdx.x * 256 + threadIdx.x;
    if (idx < 256 * 128) {                    // GEMM1: B[n][k] = W[k][n]
        const int n = idx >> 7, k = idx & 127;
        const float v = W[(size_t)k * C_MID + n];
        const __nv_bfloat16 h = __float2bfloat16(v);
        g_b1hi[n * PITCH + k] = h;
        g_b1lo[n * PITCH + k] = __float2bfloat16(v - __bfloat162float(h));
    } else {                                  // GEMM2: B[n][k] = W_fc2[k][n], 2 K-chunks
        idx -= 256 * 128;
        const int k = idx & 255, n = idx >> 8;
        const float v = W2[(size_t)k * H_DIM + n];
        const __nv_bfloat16 h = __float2bfloat16(v);
        const int off = (k >> 7) * 128 * PITCH + n * PITCH + (k & 127);
        g_b2hi[off] = h;
        g_b2lo[off] = __float2bfloat16(v - __bfloat162float(h));
    }
}

// ---------------- CSR build (deadlock-free multi-launch scan) ----------------
__global__ void hist_kernel(const int* __restrict__ ei) {
    const int e = blockIdx.x * blockDim.x + threadIdx.x;
    if (e >= E_TOT) return;
    const int dst = (e < N_EDGES) ? ei[N_EDGES + e] : (e - N_EDGES);
    atomicAdd(&g_count[dst], 1);
}
__global__ void scan1_kernel() {
    __shared__ int sh[SCAN_BLK];
    const int i = blockIdx.x * SCAN_BLK + threadIdx.x;
    const int v = (i < N_NODES) ? g_count[i] : 0;
    sh[threadIdx.x] = v;
    __syncthreads();
    for (int off = 1; off < SCAN_BLK; off <<= 1) {
        const int t = (threadIdx.x >= off) ? sh[threadIdx.x - off] : 0;
        __syncthreads();
        sh[threadIdx.x] += t;
        __syncthreads();
    }
    if (i < N_NODES) g_rowptr[i] = sh[threadIdx.x] - v;
    if (threadIdx.x == SCAN_BLK - 1) g_partial[blockIdx.x] = sh[SCAN_BLK - 1];
}
__global__ void scan2_kernel() {
    __shared__ int sh[128];
    const int t = threadIdx.x;
    const int v = (t < N_SCAN_BLKS) ? g_partial[t] : 0;
    sh[t] = v;
    __syncthreads();
    for (int off = 1; off < 128; off <<= 1) {
        const int u = (t >= off) ? sh[t - off] : 0;
        __syncthreads();
        sh[t] += u;
        __syncthreads();
    }
    if (t < N_SCAN_BLKS) g_partial[t] = sh[t] - v;
}
__global__ void scan3_kernel() {
    const int i = blockIdx.x * blockDim.x + threadIdx.x;
    if (i < N_NODES) g_rowptr[i] += g_partial[i >> 10];
}
__global__ void scatter_kernel(const int* __restrict__ ei) {
    const int e = blockIdx.x * blockDim.x + threadIdx.x;
    if (e >= E_TOT) return;
    int src, dst;
    if (e < N_EDGES) { src = ei[e]; dst = ei[N_EDGES + e]; }
    else             { src = dst = e - N_EDGES; }
    const int pos = g_rowptr[dst] + atomicAdd(&g_fill[dst], 1);
    g_ecol[pos] = src;
}

// ---------------- edge weights: w[e] = exp(lrelu(s[src]+d[dst])), winv[n]=1/sum ----
__global__ __launch_bounds__(256) void weight_kernel()
{
    const int node = blockIdx.x * 8 + (threadIdx.x >> 5);
    const int lane = threadIdx.x & 31;
    if (node >= N_NODES) return;
    const int beg = g_rowptr[node];
    const int cnt = g_count[node];
    const float dterm = g_d[node];
    float wsum = 0.f;
    for (int k = lane; k < cnt; k += 32) {
        const int src = g_ecol[beg + k];
        float e = g_s[src] + dterm;
        e = (e > 0.f) ? e : NEG_SLOPE * e;
        const float w = __expf(e);          // softmax max-shift cancels exactly
        g_w[beg + k] = w;
        wsum += w;
    }
#pragma unroll
    for (int o = 16; o > 0; o >>= 1)
        wsum += __shfl_xor_sync(0xffffffffu, wsum, o);
    if (lane == 0) g_winv[node] = 1.f / wsum;   // cnt >= 1 (self-loop)
}

// ---------------- bf16 3-pass tensor-core GEMM, 128x128 block (verified R8) ------
// EPI 0: C=xw store + fused a_src/a_dst dots -> g_s/g_d (atomic)
// EPI 1: relu(acc+bias) then fused 128->6 GEMM with W_out -> outp (no C store)
template <int EPI, int LDA, int KTOT>
__global__ __launch_bounds__(256) void gemm_bf16(
    const float* __restrict__ A,
    const __nv_bfloat16* __restrict__ Bhi, const __nv_bfloat16* __restrict__ Blo,
    const float* __restrict__ bias, float* __restrict__ C,
    const float* __restrict__ v1,   // EPI0: a_src   EPI1: W_out
    const float* __restrict__ v2,   // EPI0: a_dst   EPI1: b_out
    float* __restrict__ outp, int M)
{
    extern __shared__ char smem[];
    __nv_bfloat16* Ahi = reinterpret_cast<__nv_bfloat16*>(smem + SM_SMALL);
    __nv_bfloat16* Alo = Ahi + PLANE;
    __nv_bfloat16* Bhs = Alo + PLANE;
    __nv_bfloat16* Bls = Bhs + PLANE;
    float* sv1 = reinterpret_cast<float*>(smem);
    float* sv2 = reinterpret_cast<float*>(smem + 3072);

    const int tid = threadIdx.x;
    const int lane = tid & 31;
    const int warp = tid >> 5;
    const int warp_m = warp >> 2, warp_n = warp & 3;
    const int row0 = blockIdx.y * 128;
    const int col0 = blockIdx.x * 128;
    const int gq = lane >> 2;
    const int c2 = (lane & 3) * 2;

    if (EPI == 0) {
        if (tid < 128) { sv1[tid] = v1[col0 + tid]; sv2[tid] = v2[col0 + tid]; }
    } else {
#pragma unroll
        for (int i = 0; i < 3; i++) sv1[tid + 256 * i] = v1[tid + 256 * i];
        if (tid < 128) sv2[tid] = bias[tid];
    }

    float acc[4][4][4];
#pragma unroll
    for (int mt = 0; mt < 4; mt++)
#pragma unroll
        for (int nt = 0; nt < 4; nt++)
#pragma unroll
            for (int q = 0; q < 4; q++) acc[mt][nt][q] = 0.f;

    constexpr int NCHUNK = KTOT / 128;
    for (int chunk = 0; chunk < NCHUNK; chunk++) {
        // ---- stage A: split fp32 -> hi/lo bf16 ----
        {
            const int r = tid >> 1, h = (tid & 1) * 64;
            const bool ok = (row0 + r) < M;
            const float4* ap = reinterpret_cast<const float4*>(
                A + (size_t)(row0 + r) * LDA + chunk * 128 + h);
#pragma unroll
            for (int j = 0; j < 16; j++) {
                float4 v = make_float4(0.f, 0.f, 0.f, 0.f);
                if (ok) v = ap[j];
                const int off = r * PITCH + h + 4 * j;
                split_store(Ahi, Alo, off, v.x, v.y);
                split_store(Ahi, Alo, off + 2, v.z, v.w);
            }
        }
        // ---- stage B: plain copy of pre-split planes ----
        {
            const size_t boff = (size_t)(chunk * 128 + col0) * PITCH;
            const float4* sh = reinterpret_cast<const float4*>(Bhi + boff);
            const float4* sl = reinterpret_cast<const float4*>(Blo + boff);
            float4* dh = reinterpret_cast<float4*>(Bhs);
            float4* dl = reinterpret_cast<float4*>(Bls);
            for (int i = tid; i < PLANE / 8; i += 256) { dh[i] = sh[i]; dl[i] = sl[i]; }
        }
        __syncthreads();

        // ---- mainloop: 8 k-steps of 16, 3 passes, no syncs ----
#pragma unroll
        for (int ks = 0; ks < 8; ks++) {
            const int kk = ks * 16;
            uint32_t ahi[4][4], alo[4][4];
#pragma unroll
            for (int mt = 0; mt < 4; mt++) {
                const int r = warp_m * 64 + mt * 16 + gq;
                ahi[mt][0] = *reinterpret_cast<const uint32_t*>(&Ahi[r * PITCH + kk + c2]);
                ahi[mt][1] = *reinterpret_cast<const uint32_t*>(&Ahi[(r + 8) * PITCH + kk + c2]);
                ahi[mt][2] = *reinterpret_cast<const uint32_t*>(&Ahi[r * PITCH + kk + c2 + 8]);
                ahi[mt][3] = *reinterpret_cast<const uint32_t*>(&Ahi[(r + 8) * PITCH + kk + c2 + 8]);
                alo[mt][0] = *reinterpret_cast<const uint32_t*>(&Alo[r * PITCH + kk + c2]);
                alo[mt][1] = *reinterpret_cast<const uint32_t*>(&Alo[(r + 8) * PITCH + kk + c2]);
                alo[mt][2] = *reinterpret_cast<const uint32_t*>(&Alo[r * PITCH + kk + c2 + 8]);
                alo[mt][3] = *reinterpret_cast<const uint32_t*>(&Alo[(r + 8) * PITCH + kk + c2 + 8]);
            }
            uint32_t bhi[4][2], blo[4][2];
#pragma unroll
            for (int nt = 0; nt < 4; nt++) {
                const int n = warp_n * 32 + nt * 8 + gq;
                bhi[nt][0] = *reinterpret_cast<const uint32_t*>(&Bhs[n * PITCH + kk + c2]);
                bhi[nt][1] = *reinterpret_cast<const uint32_t*>(&Bhs[n * PITCH + kk + c2 + 8]);
                blo[nt][0] = *reinterpret_cast<const uint32_t*>(&Bls[n * PITCH + kk + c2]);
                blo[nt][1] = *reinterpret_cast<const uint32_t*>(&Bls[n * PITCH + kk + c2 + 8]);
            }
#pragma unroll
            for (int mt = 0; mt < 4; mt++)
#pragma unroll
                for (int nt = 0; nt < 4; nt++) {
                    mma_bf16(acc[mt][nt], ahi[mt], bhi[nt][0], bhi[nt][1]);
                    mma_bf16(acc[mt][nt], ahi[mt], blo[nt][0], blo[nt][1]);
                    mma_bf16(acc[mt][nt], alo[mt], bhi[nt][0], bhi[nt][1]);
                }
        }
        __syncthreads();
    }

    if (EPI == 0) {
        // ---- store C + fused a_src/a_dst dots ----
#pragma unroll
        for (int mt = 0; mt < 4; mt++) {
            const int r = row0 + warp_m * 64 + mt * 16 + gq;
#pragma unroll
            for (int nt = 0; nt < 4; nt++) {
                const int c = col0 + warp_n * 32 + nt * 8 + c2;
                if (r < M)
                    *reinterpret_cast<float2*>(C + (size_t)r * C_MID + c) =
                        make_float2(acc[mt][nt][0], acc[mt][nt][1]);
                if (r + 8 < M)
                    *reinterpret_cast<float2*>(C + (size_t)(r + 8) * C_MID + c) =
                        make_float2(acc[mt][nt][2], acc[mt][nt][3]);
            }
        }
        float avv[4][2], dvv[4][2];
#pragma unroll
        for (int nt = 0; nt < 4; nt++) {
            const int lc = warp_n * 32 + nt * 8 + c2;
            avv[nt][0] = sv1[lc]; avv[nt][1] = sv1[lc + 1];
            dvv[nt][0] = sv2[lc]; dvv[nt][1] = sv2[lc + 1];
        }
#pragma unroll
        for (int mt = 0; mt < 4; mt++) {
            float ps0 = 0.f, pd0 = 0.f, ps8 = 0.f, pd8 = 0.f;
#pragma unroll
            for (int nt = 0; nt < 4; nt++) {
                ps0 = fmaf(acc[mt][nt][0], avv[nt][0], fmaf(acc[mt][nt][1], avv[nt][1], ps0));
                pd0 = fmaf(acc[mt][nt][0], dvv[nt][0], fmaf(acc[mt][nt][1], dvv[nt][1], pd0));
                ps8 = fmaf(acc[mt][nt][2], avv[nt][0], fmaf(acc[mt][nt][3], avv[nt][1], ps8));
                pd8 = fmaf(acc[mt][nt][2], dvv[nt][0], fmaf(acc[mt][nt][3], dvv[nt][1], pd8));
            }
#pragma unroll
            for (int off = 1; off <= 2; off <<= 1) {
                ps0 += __shfl_xor_sync(0xffffffffu, ps0, off);
                pd0 += __shfl_xor_sync(0xffffffffu, pd0, off);
                ps8 += __shfl_xor_sync(0xffffffffu, ps8, off);
                pd8 += __shfl_xor_sync(0xffffffffu, pd8, off);
            }
            if ((lane & 3) == 0) {
                const int r = row0 + warp_m * 64 + mt * 16 + gq;
                if (r < M)     { atomicAdd(&g_s[r], ps0);     atomicAdd(&g_d[r], pd0); }
                if (r + 8 < M) { atomicAdd(&g_s[r + 8], ps8); atomicAdd(&g_d[r + 8], pd8); }
            }
        }
    } else {
        // ---- EPI1: h = relu(acc + bias); out = h @ W_out + b_out ----
        float bb[4][2];
#pragma unroll
        for (int nt = 0; nt < 4; nt++) {
            const int lc = warp_n * 32 + nt * 8 + c2;
            bb[nt][0] = sv2[lc]; bb[nt][1] = sv2[lc + 1];
        }
#pragma unroll
        for (int mt = 0; mt < 4; mt++)
#pragma unroll
            for (int nt = 0; nt < 4; nt++) {
                acc[mt][nt][0] = fmaxf(acc[mt][nt][0] + bb[nt][0], 0.f);
                acc[mt][nt][1] = fmaxf(acc[mt][nt][1] + bb[nt][1], 0.f);
                acc[mt][nt][2] = fmaxf(acc[mt][nt][2] + bb[nt][0], 0.f);
                acc[mt][nt][3] = fmaxf(acc[mt][nt][3] + bb[nt][1], 0.f);
            }
        float* red = reinterpret_cast<float*>(smem + SM_SMALL);   // [128][25]
#pragma unroll
        for (int o = 0; o < O_DIM; o++) {
            float wv0[4], wv1[4];
#pragma unroll
            for (int nt = 0; nt < 4; nt++) {
                const int lc = warp_n * 32 + nt * 8 + c2;
                wv0[nt] = sv1[lc * O_DIM + o];
                wv1[nt] = sv1[(lc + 1) * O_DIM + o];
            }
#pragma unroll
            for (int mt = 0; mt < 4; mt++) {
                float p0 = 0.f, p8 = 0.f;
#pragma unroll
                for (int nt = 0; nt < 4; nt++) {
                    p0 = fmaf(acc[mt][nt][0], wv0[nt], fmaf(acc[mt][nt][1], wv1[nt], p0));
                    p8 = fmaf(acc[mt][nt][2], wv0[nt], fmaf(acc[mt][nt][3], wv1[nt], p8));
                }
#pragma unroll
                for (int off = 1; off <= 2; off <<= 1) {
                    p0 += __shfl_xor_sync(0xffffffffu, p0, off);
                    p8 += __shfl_xor_sync(0xffffffffu, p8, off);
                }
                if ((lane & 3) == 0) {
                    const int rl = warp_m * 64 + mt * 16 + gq;
                    red[rl * 25 + warp_n * 6 + o] = p0;
                    red[(rl + 8) * 25 + warp_n * 6 + o] = p8;
                }
            }
        }
        __syncthreads();
        if (tid < 128) {
            const int r = row0 + tid;
            if (r < M) {
#pragma unroll
                for (int o = 0; o < O_DIM; o++) {
                    const float s = red[tid * 25 + o] + red[tid * 25 + 6 + o]
                                  + red[tid * 25 + 12 + o] + red[tid * 25 + 18 + o];
                    outp[(size_t)r * O_DIM + o] = s + v2[o];
                }
            }
        }
    }
}

// ---------------- CSR aggregate over one 128-col half (R8 shape, untouched) ------
template <int HALF>
__global__ __launch_bounds__(256) void agg_half_kernel(const float* __restrict__ bias)
{
    const int node = blockIdx.x * 8 + (threadIdx.x >> 5);
    const int t    = threadIdx.x & 31;
    if (node >= N_NODES) return;

    const int beg = g_rowptr[node];
    const int cnt = g_count[node];

    float4 acc = make_float4(0.f, 0.f, 0.f, 0.f);
    for (int k = 0; k < cnt; k++) {
        const int src = g_ecol[beg + k];
        const float w = g_w[beg + k];
        const float4 v = *reinterpret_cast<const float4*>(
            g_xw + (size_t)src * C_MID + HALF * 128 + t * 4);
        acc.x = fmaf(w, v.x, acc.x);
        acc.y = fmaf(w, v.y, acc.y);
        acc.z = fmaf(w, v.z, acc.z);
        acc.w = fmaf(w, v.w, acc.w);
    }

    const float inv = g_winv[node];
    const float4 bb = reinterpret_cast<const float4*>(bias)[HALF * 32 + t];
    float4 o;
    o.x = fmaxf(fmaf(acc.x, inv, bb.x), 0.f);
    o.y = fmaxf(fmaf(acc.y, inv, bb.y), 0.f);
    o.z = fmaxf(fmaf(acc.z, inv, bb.z), 0.f);
    o.w = fmaxf(fmaf(acc.w, inv, bb.w), 0.f);
    *reinterpret_cast<float4*>(
        g_gat + (size_t)node * C_MID + HALF * 128 + t * 4) = o;
}

// ---------------- launch ----------------
extern "C" void kernel_launch(void* const* d_in, const int* in_sizes, int n_in,
                              void* d_out, int out_size)
{
    const float* x      = (const float*)d_in[0];
    const int*   ei     = (const int*)  d_in[1];
    const float* W      = (const float*)d_in[2];
    const float* a_src  = (const float*)d_in[3];
    const float* a_dst  = (const float*)d_in[4];
    const float* b      = (const float*)d_in[5];
    const float* W_fc2  = (const float*)d_in[6];
    const float* b_fc2  = (const float*)d_in[7];
    const float* W_out  = (const float*)d_in[8];
    const float* b_out  = (const float*)d_in[9];
    float* out = (float*)d_out;

    float *xw, *gat;
    __nv_bfloat16 *b1h, *b1l, *b2h, *b2l;
    cudaGetSymbolAddress((void**)&xw,  g_xw);
    cudaGetSymbolAddress((void**)&gat, g_gat);
    cudaGetSymbolAddress((void**)&b1h, g_b1hi);
    cudaGetSymbolAddress((void**)&b1l, g_b1lo);
    cudaGetSymbolAddress((void**)&b2h, g_b2hi);
    cudaGetSymbolAddress((void**)&b2l, g_b2lo);

    static bool inited = false;
    static cudaStream_t sB;
    static cudaEvent_t evFork, evJoin;
    if (!inited) {
        cudaFuncSetAttribute((const void*)gemm_bf16<0, F_IN, 128>,
                             cudaFuncAttributeMaxDynamicSharedMemorySize, SM_TOTAL);
        cudaFuncSetAttribute((const void*)gemm_bf16<1, C_MID, 256>,
                             cudaFuncAttributeMaxDynamicSharedMemorySize, SM_TOTAL);
        cudaStreamCreateWithFlags(&sB, cudaStreamNonBlocking);
        cudaEventCreateWithFlags(&evFork, cudaEventDisableTiming);
        cudaEventCreateWithFlags(&evJoin, cudaEventDisableTiming);
        inited = true;
    }

    const int nblk = (N_NODES + 127) / 128;   // 782

    // 1) init (zeroes counts/fill/s/d) on main stream
    init_kernel<<<(N_NODES + 255) / 256, 256>>>();

    // 2) fork: CSR build on side stream (deadlock-free multi-launch scan),
    //    overlapped with prep + GEMM1 on the main stream
    cudaEventRecord(evFork, 0);
    cudaStreamWaitEvent(sB, evFork, 0);
    hist_kernel<<<(E_TOT + 255) / 256, 256, 0, sB>>>(ei);
    scan1_kernel<<<N_SCAN_BLKS, SCAN_BLK, 0, sB>>>();
    scan2_kernel<<<1, 128, 0, sB>>>();
    scan3_kernel<<<(N_NODES + 255) / 256, 256, 0, sB>>>();
    scatter_kernel<<<(E_TOT + 255) / 256, 256, 0, sB>>>(ei);
    cudaEventRecord(evJoin, sB);

    // 3) prep + GEMM1 on main stream (independent of CSR)
    prep_kernel<<<256, 256>>>(W, W_fc2);
    {
        dim3 grid(C_MID / 128, nblk);
        gemm_bf16<0, F_IN, 128><<<grid, 256, SM_TOTAL>>>(
            x, b1h, b1l, nullptr, xw, a_src, a_dst, nullptr, N_NODES);
    }

    // join: weight needs CSR (rowptr/ecol) and GEMM1 (g_s/g_d)
    cudaStreamWaitEvent(0, evJoin, 0);

    // 4) edge softmax weights, then two L2-resident half-column gather passes
    weight_kernel<<<(N_NODES + 7) / 8, 256>>>();
    agg_half_kernel<0><<<(N_NODES + 7) / 8, 256>>>(b);
    agg_half_kernel<1><<<(N_NODES + 7) / 8, 256>>>(b);

    // 5+6) out = relu(h2 @ W_fc2 + b_fc2) @ W_out + b_out (bf16 3-pass, fused)
    {
        dim3 grid(1, nblk);
        gemm_bf16<1, C_MID, 256><<<grid, 256, SM_TOTAL>>>(
            gat, b2h, b2l, b_fc2, nullptr, W_out, b_out, out, N_NODES);
    }
}